// round 1
// baseline (speedup 1.0000x reference)
#include <cuda_runtime.h>

#define BB 8
#define CC 128
#define NH 128
#define NW 128
#define C1 50
#define C2 18
#define HH 512
#define WW 512

// Scratch (device globals — no allocations allowed)
__device__ float g_h[(size_t)BB * C1 * NH * NW];     // conv1+relu+bn output
__device__ float g_cond[(size_t)BB * C2 * NH * NW];  // conv2 output

// ---------------------------------------------------------------------------
// Kernel 1: conv1 (3x3, 128->50, pad 1) + ReLU + BatchNorm (inference)
// Block: 32x8 threads, tile 32x16 pixels, each thread 2 pixels (ty, ty+8),
// 25 output channels per block-half. cin chunked by 4 through smem.
// ---------------------------------------------------------------------------
__global__ __launch_bounds__(256) void conv1_kernel(
    const float* __restrict__ ctrl, const float* __restrict__ w1,
    const float* __restrict__ b1, const float* __restrict__ gamma,
    const float* __restrict__ beta, const float* __restrict__ mean,
    const float* __restrict__ var)
{
    const int tx = threadIdx.x, ty = threadIdx.y;
    const int tid = ty * 32 + tx;
    const int tileX0 = blockIdx.x * 32;
    const int tileY0 = blockIdx.y * 16;
    const int b = blockIdx.z >> 1;
    const int half = blockIdx.z & 1;

    __shared__ float in_s[4][18][34];
    __shared__ float w_s[25][4][9];

    float acc0[25], acc1[25];
#pragma unroll
    for (int i = 0; i < 25; i++) { acc0[i] = 0.f; acc1[i] = 0.f; }

    const float* ctrl_b = ctrl + (size_t)b * CC * NH * NW;

    for (int c0 = 0; c0 < CC; c0 += 4) {
        __syncthreads();
        // load haloed input tile: 4 cin x 18 rows x 34 cols (zero-padded)
        for (int e = tid; e < 4 * 18 * 34; e += 256) {
            int c = e / (18 * 34);
            int rem = e - c * (18 * 34);
            int r = rem / 34, col = rem - r * 34;
            int gy = tileY0 + r - 1;
            int gx = tileX0 + col - 1;
            float v = 0.f;
            if ((unsigned)gy < NH && (unsigned)gx < NW)
                v = ctrl_b[((size_t)(c0 + c) * NH + gy) * NW + gx];
            in_s[c][r][col] = v;
        }
        // load weights: 25 oc x 4 cin x 9 taps
        for (int e = tid; e < 25 * 4 * 9; e += 256) {
            int oc = e / 36;
            int rem = e - oc * 36;
            int c = rem / 9, t = rem - c * 9;
            w_s[oc][c][t] = w1[((size_t)(half * 25 + oc) * CC + (c0 + c)) * 9 + t];
        }
        __syncthreads();

        for (int c = 0; c < 4; c++) {
            float v0[9], v1[9];
#pragma unroll
            for (int dy = 0; dy < 3; dy++)
#pragma unroll
                for (int dx = 0; dx < 3; dx++) {
                    v0[dy * 3 + dx] = in_s[c][ty + dy][tx + dx];
                    v1[dy * 3 + dx] = in_s[c][ty + 8 + dy][tx + dx];
                }
#pragma unroll
            for (int oc = 0; oc < 25; oc++) {
#pragma unroll
                for (int t = 0; t < 9; t++) {
                    float wv = w_s[oc][c][t];
                    acc0[oc] += v0[t] * wv;
                    acc1[oc] += v1[t] * wv;
                }
            }
        }
    }

    const int y0 = tileY0 + ty, y1 = y0 + 8;
    const int x = tileX0 + tx;
#pragma unroll
    for (int oc = 0; oc < 25; oc++) {
        int o = half * 25 + oc;
        float s = gamma[o] * rsqrtf(var[o] + 1e-5f);
        float bn_b = beta[o] - mean[o] * s;
        float a0 = fmaxf(acc0[oc] + b1[o], 0.f) * s + bn_b;
        float a1 = fmaxf(acc1[oc] + b1[o], 0.f) * s + bn_b;
        g_h[(((size_t)b * C1 + o) * NH + y0) * NW + x] = a0;
        g_h[(((size_t)b * C1 + o) * NH + y1) * NW + x] = a1;
    }
}

// ---------------------------------------------------------------------------
// Kernel 2: conv2 (3x3, 50->18, pad 1) + bias
// Same scheme: 32x16 tile, 2 px/thread, 18 oc, cin chunked by 5.
// ---------------------------------------------------------------------------
__global__ __launch_bounds__(256) void conv2_kernel(
    const float* __restrict__ w2, const float* __restrict__ b2)
{
    const int tx = threadIdx.x, ty = threadIdx.y;
    const int tid = ty * 32 + tx;
    const int tileX0 = blockIdx.x * 32;
    const int tileY0 = blockIdx.y * 16;
    const int b = blockIdx.z;

    __shared__ float in_s[5][18][34];
    __shared__ float w_s[18][5][9];

    float acc0[18], acc1[18];
#pragma unroll
    for (int i = 0; i < 18; i++) { acc0[i] = 0.f; acc1[i] = 0.f; }

    const float* h_b = g_h + (size_t)b * C1 * NH * NW;

    for (int c0 = 0; c0 < C1; c0 += 5) {
        __syncthreads();
        for (int e = tid; e < 5 * 18 * 34; e += 256) {
            int c = e / (18 * 34);
            int rem = e - c * (18 * 34);
            int r = rem / 34, col = rem - r * 34;
            int gy = tileY0 + r - 1;
            int gx = tileX0 + col - 1;
            float v = 0.f;
            if ((unsigned)gy < NH && (unsigned)gx < NW)
                v = h_b[((size_t)(c0 + c) * NH + gy) * NW + gx];
            in_s[c][r][col] = v;
        }
        for (int e = tid; e < 18 * 5 * 9; e += 256) {
            int oc = e / 45;
            int rem = e - oc * 45;
            int c = rem / 9, t = rem - c * 9;
            w_s[oc][c][t] = w2[((size_t)oc * C1 + (c0 + c)) * 9 + t];
        }
        __syncthreads();

        for (int c = 0; c < 5; c++) {
            float v0[9], v1[9];
#pragma unroll
            for (int dy = 0; dy < 3; dy++)
#pragma unroll
                for (int dx = 0; dx < 3; dx++) {
                    v0[dy * 3 + dx] = in_s[c][ty + dy][tx + dx];
                    v1[dy * 3 + dx] = in_s[c][ty + 8 + dy][tx + dx];
                }
#pragma unroll
            for (int oc = 0; oc < 18; oc++) {
#pragma unroll
                for (int t = 0; t < 9; t++) {
                    float wv = w_s[oc][c][t];
                    acc0[oc] += v0[t] * wv;
                    acc1[oc] += v1[t] * wv;
                }
            }
        }
    }

    const int y0 = tileY0 + ty, y1 = y0 + 8;
    const int x = tileX0 + tx;
#pragma unroll
    for (int oc = 0; oc < 18; oc++) {
        g_cond[(((size_t)b * C2 + oc) * NH + y0) * NW + x] = acc0[oc] + b2[oc];
        g_cond[(((size_t)b * C2 + oc) * NH + y1) * NW + x] = acc1[oc] + b2[oc];
    }
}

// ---------------------------------------------------------------------------
// Kernel 3: translate — out[b,ch,y,x] = sum_k img[b,ch,y+4j-4,x+4i-4]*w_k
// with w_k = cond[b,(ch/3)*9+k, y/4, x/4], k = i*3+j, OOB image = 0.
// Shifts are multiples of 4 -> float4 loads stay 16B-aligned.
// Thread = one 4x4 cell (one float4 wide x 4 rows): weights loaded once/16px.
// ---------------------------------------------------------------------------
__global__ __launch_bounds__(256) void translate_kernel(
    const float* __restrict__ image, float* __restrict__ out)
{
    const int x4 = threadIdx.x;                       // 0..127 (float4 col = cell col)
    const int cellY = blockIdx.x * 2 + threadIdx.y;   // 0..127
    const int ch = blockIdx.y;                        // 0..5
    const int b = blockIdx.z;                         // 0..7
    const int g = ch / 3;

    float wk[9];
    const float* cond_b = g_cond + ((size_t)b * C2 + g * 9) * NH * NW;
#pragma unroll
    for (int k = 0; k < 9; k++)
        wk[k] = cond_b[(size_t)k * NH * NW + (size_t)cellY * NW + x4];

    const float4* img4 = (const float4*)image + (size_t)(b * 6 + ch) * HH * (WW / 4);
    float4* out4 = (float4*)out + (size_t)(b * 6 + ch) * HH * (WW / 4);

#pragma unroll
    for (int r = 0; r < 4; r++) {
        int y = cellY * 4 + r;
        float4 acc = make_float4(0.f, 0.f, 0.f, 0.f);
#pragma unroll
        for (int i = 0; i < 3; i++) {
            int xf = x4 + i - 1;
            if ((unsigned)xf >= (unsigned)(WW / 4)) continue;
#pragma unroll
            for (int j = 0; j < 3; j++) {
                int yy = y + j * 4 - 4;
                if ((unsigned)yy >= (unsigned)HH) continue;
                float w = wk[i * 3 + j];
                float4 v = img4[(size_t)yy * (WW / 4) + xf];
                acc.x += v.x * w; acc.y += v.y * w;
                acc.z += v.z * w; acc.w += v.w * w;
            }
        }
        out4[(size_t)y * (WW / 4) + x4] = acc;
    }
}

// ---------------------------------------------------------------------------
extern "C" void kernel_launch(void* const* d_in, const int* in_sizes, int n_in,
                              void* d_out, int out_size)
{
    const float* image = (const float*)d_in[0];
    const float* ctrl  = (const float*)d_in[1];
    const float* w1    = (const float*)d_in[2];
    const float* b1    = (const float*)d_in[3];
    const float* gamma = (const float*)d_in[4];
    const float* beta  = (const float*)d_in[5];
    const float* mean  = (const float*)d_in[6];
    const float* var   = (const float*)d_in[7];
    const float* w2    = (const float*)d_in[8];
    const float* b2    = (const float*)d_in[9];
    float* out = (float*)d_out;

    conv1_kernel<<<dim3(NW / 32, NH / 16, BB * 2), dim3(32, 8)>>>(
        ctrl, w1, b1, gamma, beta, mean, var);
    conv2_kernel<<<dim3(NW / 32, NH / 16, BB), dim3(32, 8)>>>(w2, b2);
    translate_kernel<<<dim3(64, 6, BB), dim3(128, 2)>>>(image, out);
}

// round 4
// speedup vs baseline: 1.9893x; 1.9893x over previous
#include <cuda_runtime.h>
#include <cuda_bf16.h>
#include <cstdint>

#define BB 8
#define CC 128
#define NH 128
#define NW 128
#define C1 50
#define C2 18
#define HH 512
#define WW 512

// Scratch (device globals — no allocations allowed)
__device__ float g_h[(size_t)BB * C1 * NH * NW];     // conv1+relu+bn output
__device__ float g_cond[(size_t)BB * C2 * NH * NW];  // conv2 output
// conv1 weights, bf16 hi/lo, ldmatrix-ready: [chunk8][tap9][hilo2][oc64][cin16]
__device__ __align__(16) __nv_bfloat16 g_w1p[8 * 9 * 2 * 64 * 16];

__device__ __forceinline__ uint32_t smem_u32(const void* p) {
    uint32_t a;
    asm("{ .reg .u64 t; cvta.to.shared.u64 t, %1; cvt.u32.u64 %0, t; }"
        : "=r"(a) : "l"(p));
    return a;
}

#define LDSM4(r, a)                                                            \
    asm volatile("ldmatrix.sync.aligned.m8n8.x4.shared.b16 {%0,%1,%2,%3}, [%4];" \
        : "=r"((r)[0]), "=r"((r)[1]), "=r"((r)[2]), "=r"((r)[3]) : "r"(a))

#define MMA16816(c, a, b0, b1)                                                 \
    asm volatile("mma.sync.aligned.m16n8k16.row.col.f32.bf16.bf16.f32 "        \
        "{%0,%1,%2,%3},{%4,%5,%6,%7},{%8,%9},{%0,%1,%2,%3};"                   \
        : "+f"((c)[0]), "+f"((c)[1]), "+f"((c)[2]), "+f"((c)[3])               \
        : "r"((a)[0]), "r"((a)[1]), "r"((a)[2]), "r"((a)[3]), "r"(b0), "r"(b1))

// ---------------------------------------------------------------------------
// Prep: split conv1 weights to bf16 hi/lo in ldmatrix layout.
// idx = (((chunk*9 + tap)*2 + h)*64 + oc)*16 + jc
// ---------------------------------------------------------------------------
__global__ void prep_w1_kernel(const float* __restrict__ w1) {
    int idx = blockIdx.x * 256 + threadIdx.x;
    if (idx >= 8 * 9 * 2 * 64 * 16) return;
    int jc = idx & 15;
    int oc = (idx >> 4) & 63;
    int h = (idx >> 10) & 1;
    int r = idx >> 11;
    int tap = r % 9, chunk = r / 9;
    int dy = tap / 3, dx = tap % 3;
    float w = 0.f;
    if (oc < C1)
        w = w1[((oc * CC + chunk * 16 + jc) * 3 + dy) * 3 + dx];
    __nv_bfloat16 hi = __float2bfloat16(w);
    g_w1p[idx] = (h == 0) ? hi : __float2bfloat16(w - __bfloat162float(hi));
}

// ---------------------------------------------------------------------------
// conv1 via mma.sync bf16 (3-term hi/lo split) + fused bias/ReLU/BN.
// CTA = (b, y). M=128 px, N=64 oc, K = 9 taps x 128 cin.
// smem: B [tap9][hilo2][oc64] rows 32B data + 16B pad (48B stride)
//       A [dy3][hilo2][130 px] rows 32B data + 16B pad
// ---------------------------------------------------------------------------
#define OFF_B 0
#define B_REGION 3072              // 64 rows * 48B
#define OFF_A (9 * 2 * B_REGION)   // 55296
#define A_REGION 6240              // 130 rows * 48B
#define SMEM_TOTAL (OFF_A + 6 * A_REGION)  // 92736

__global__ void __launch_bounds__(256, 2) conv1_mma_kernel(
    const float* __restrict__ ctrl, const float* __restrict__ b1,
    const float* __restrict__ gamma, const float* __restrict__ beta,
    const float* __restrict__ mean, const float* __restrict__ var)
{
    extern __shared__ char smem[];
    float* smemF = (float*)smem;
    const uint32_t sb = smem_u32(smem);
    const int tid = threadIdx.x;
    const int lane = tid & 31;
    const int warp = tid >> 5;
    const int b = blockIdx.x >> 7;
    const int y = blockIdx.x & 127;
    const int wm = (warp >> 1) * 32;   // px base
    const int wn = (warp & 1) * 32;    // oc base

    // per-lane ldmatrix address components
    const int rA = (lane & 7) + ((lane >> 3) & 1) * 8;   // A row within m16
    const int kbA = (lane >> 4) * 16;                    // A k-byte offset
    const int ocB = (lane & 7) + ((lane >> 4) << 3);     // B oc row within n16
    const int kbB = ((lane >> 3) & 1) * 16;              // B k-byte offset

    const uint32_t aBase = sb + OFF_A + (uint32_t)(wm + rA) * 48 + kbA;
    const uint32_t bBase = sb + OFF_B + (uint32_t)(wn + ocB) * 48 + kbB;

    float C[2][4][4];
#pragma unroll
    for (int i = 0; i < 2; i++)
#pragma unroll
        for (int j = 0; j < 4; j++)
#pragma unroll
            for (int k = 0; k < 4; k++) C[i][j][k] = 0.f;

    for (int chunk = 0; chunk < 8; chunk++) {
        __syncthreads();
        // ---- stage B: straight copy of pre-split weights, 48B-stride rows
        {
            const float4* srcB = ((const float4*)g_w1p) + chunk * 2304;
            for (int e = tid; e < 2304; e += 256) {
                int r = e >> 1, q = e & 1;
                *(float4*)(smem + OFF_B + (r >> 6) * B_REGION + (r & 63) * 48 + q * 16) =
                    srcB[e];
            }
        }
        // ---- stage A: 3 dy rows, fp32 -> hi/lo bf16, transposed [px][cin]
        for (int dy = 0; dy < 3; dy++) {
            int gy = y + dy - 1;
            char* Ah = smem + OFF_A + (dy * 2 + 0) * A_REGION;
            char* Al = smem + OFF_A + (dy * 2 + 1) * A_REGION;
            if ((unsigned)gy < (unsigned)NH) {
                const float* src =
                    ctrl + (((size_t)b * CC + chunk * 16) * NH + gy) * NW;
                for (int e = tid; e < 512; e += 256) {
                    int c = e & 15, q = e >> 4;
                    float4 v = *(const float4*)(src + (size_t)c * NH * NW + 4 * q);
                    float vv[4] = {v.x, v.y, v.z, v.w};
#pragma unroll
                    for (int j = 0; j < 4; j++) {
                        int row = 4 * q + 1 + j;
                        __nv_bfloat16 hi = __float2bfloat16(vv[j]);
                        __nv_bfloat16 lo =
                            __float2bfloat16(vv[j] - __bfloat162float(hi));
                        *(__nv_bfloat16*)(Ah + row * 48 + c * 2) = hi;
                        *(__nv_bfloat16*)(Al + row * 48 + c * 2) = lo;
                    }
                }
                if (tid < 32) {  // x halo columns are always zero
                    int c = tid & 15, row = (tid >> 4) * 129;
                    *(__nv_bfloat16*)(Ah + row * 48 + c * 2) = __float2bfloat16(0.f);
                    *(__nv_bfloat16*)(Al + row * 48 + c * 2) = __float2bfloat16(0.f);
                }
            } else {
                for (int e = tid; e < 16 * 130; e += 256) {
                    int c = e & 15, row = e >> 4;
                    *(__nv_bfloat16*)(Ah + row * 48 + c * 2) = __float2bfloat16(0.f);
                    *(__nv_bfloat16*)(Al + row * 48 + c * 2) = __float2bfloat16(0.f);
                }
            }
        }
        __syncthreads();

        // ---- mma over 9 taps
#pragma unroll
        for (int dy = 0; dy < 3; dy++) {
#pragma unroll
            for (int dx = 0; dx < 3; dx++) {
                const int tap = dy * 3 + dx;
                uint32_t ah[8], al[8], bh[8], bl[8];
                uint32_t aH = aBase + (dy * 2) * A_REGION + dx * 48;
                uint32_t aL = aH + A_REGION;
                LDSM4(ah, aH);
                LDSM4(ah + 4, aH + 16 * 48);
                LDSM4(al, aL);
                LDSM4(al + 4, aL + 16 * 48);
                uint32_t bH = bBase + (tap * 2) * B_REGION;
                uint32_t bL = bH + B_REGION;
                LDSM4(bh, bH);
                LDSM4(bh + 4, bH + 16 * 48);
                LDSM4(bl, bL);
                LDSM4(bl + 4, bL + 16 * 48);
#pragma unroll
                for (int mt = 0; mt < 2; mt++) {
#pragma unroll
                    for (int nt = 0; nt < 4; nt++) {
                        MMA16816(C[mt][nt], ah + mt * 4, bh[nt * 2], bh[nt * 2 + 1]);
                        MMA16816(C[mt][nt], al + mt * 4, bh[nt * 2], bh[nt * 2 + 1]);
                        MMA16816(C[mt][nt], ah + mt * 4, bl[nt * 2], bl[nt * 2 + 1]);
                    }
                }
            }
        }
    }

    // ---- epilogue: transpose through smem [oc64][132], fused bias/ReLU/BN
    __syncthreads();
    {
        const int g = lane >> 2, t = lane & 3;
#pragma unroll
        for (int mt = 0; mt < 2; mt++) {
#pragma unroll
            for (int nt = 0; nt < 4; nt++) {
                int px = wm + mt * 16 + g;
                int oc = wn + nt * 8 + 2 * t;
                smemF[oc * 132 + px] = C[mt][nt][0];
                smemF[(oc + 1) * 132 + px] = C[mt][nt][1];
                smemF[oc * 132 + px + 8] = C[mt][nt][2];
                smemF[(oc + 1) * 132 + px + 8] = C[mt][nt][3];
            }
        }
    }
    __syncthreads();
    for (int e = tid; e < 64 * 32; e += 256) {
        int oc = e >> 5, q = e & 31;
        if (oc < C1) {
            float s = gamma[oc] * rsqrtf(var[oc] + 1e-5f);
            float bb = beta[oc] - mean[oc] * s;
            float bias = b1[oc];
            float4 v = *(float4*)(smemF + oc * 132 + 4 * q);
            v.x = fmaxf(v.x + bias, 0.f) * s + bb;
            v.y = fmaxf(v.y + bias, 0.f) * s + bb;
            v.z = fmaxf(v.z + bias, 0.f) * s + bb;
            v.w = fmaxf(v.w + bias, 0.f) * s + bb;
            *(float4*)(g_h + (((size_t)b * C1 + oc) * NH + y) * NW + 4 * q) = v;
        }
    }
}

// ---------------------------------------------------------------------------
// Kernel 2: conv2 (3x3, 50->18, pad 1) + bias  (CUDA-core)
// ---------------------------------------------------------------------------
__global__ __launch_bounds__(256) void conv2_kernel(
    const float* __restrict__ w2, const float* __restrict__ b2)
{
    const int tx = threadIdx.x, ty = threadIdx.y;
    const int tid = ty * 32 + tx;
    const int tileX0 = blockIdx.x * 32;
    const int tileY0 = blockIdx.y * 16;
    const int b = blockIdx.z;

    __shared__ float in_s[5][18][34];
    __shared__ float w_s[18][5][9];

    float acc0[18], acc1[18];
#pragma unroll
    for (int i = 0; i < 18; i++) { acc0[i] = 0.f; acc1[i] = 0.f; }

    const float* h_b = g_h + (size_t)b * C1 * NH * NW;

    for (int c0 = 0; c0 < C1; c0 += 5) {
        __syncthreads();
        for (int e = tid; e < 5 * 18 * 34; e += 256) {
            int c = e / (18 * 34);
            int rem = e - c * (18 * 34);
            int r = rem / 34, col = rem - r * 34;
            int gy = tileY0 + r - 1;
            int gx = tileX0 + col - 1;
            float v = 0.f;
            if ((unsigned)gy < NH && (unsigned)gx < NW)
                v = h_b[((size_t)(c0 + c) * NH + gy) * NW + gx];
            in_s[c][r][col] = v;
        }
        for (int e = tid; e < 18 * 5 * 9; e += 256) {
            int oc = e / 45;
            int rem = e - oc * 45;
            int c = rem / 9, t = rem - c * 9;
            w_s[oc][c][t] = w2[((size_t)oc * C1 + (c0 + c)) * 9 + t];
        }
        __syncthreads();

        for (int c = 0; c < 5; c++) {
            float v0[9], v1[9];
#pragma unroll
            for (int dy = 0; dy < 3; dy++)
#pragma unroll
                for (int dxx = 0; dxx < 3; dxx++) {
                    v0[dy * 3 + dxx] = in_s[c][ty + dy][tx + dxx];
                    v1[dy * 3 + dxx] = in_s[c][ty + 8 + dy][tx + dxx];
                }
#pragma unroll
            for (int oc = 0; oc < 18; oc++) {
#pragma unroll
                for (int t = 0; t < 9; t++) {
                    float wv = w_s[oc][c][t];
                    acc0[oc] += v0[t] * wv;
                    acc1[oc] += v1[t] * wv;
                }
            }
        }
    }

    const int y0 = tileY0 + ty, y1 = y0 + 8;
    const int x = tileX0 + tx;
#pragma unroll
    for (int oc = 0; oc < 18; oc++) {
        g_cond[(((size_t)b * C2 + oc) * NH + y0) * NW + x] = acc0[oc] + b2[oc];
        g_cond[(((size_t)b * C2 + oc) * NH + y1) * NW + x] = acc1[oc] + b2[oc];
    }
}

// ---------------------------------------------------------------------------
// Kernel 3: translate
// ---------------------------------------------------------------------------
__global__ __launch_bounds__(256) void translate_kernel(
    const float* __restrict__ image, float* __restrict__ out)
{
    const int x4 = threadIdx.x;
    const int cellY = blockIdx.x * 2 + threadIdx.y;
    const int ch = blockIdx.y;
    const int b = blockIdx.z;
    const int g = ch / 3;

    float wk[9];
    const float* cond_b = g_cond + ((size_t)b * C2 + g * 9) * NH * NW;
#pragma unroll
    for (int k = 0; k < 9; k++)
        wk[k] = cond_b[(size_t)k * NH * NW + (size_t)cellY * NW + x4];

    const float4* img4 = (const float4*)image + (size_t)(b * 6 + ch) * HH * (WW / 4);
    float4* out4 = (float4*)out + (size_t)(b * 6 + ch) * HH * (WW / 4);

#pragma unroll
    for (int r = 0; r < 4; r++) {
        int y = cellY * 4 + r;
        float4 acc = make_float4(0.f, 0.f, 0.f, 0.f);
#pragma unroll
        for (int i = 0; i < 3; i++) {
            int xf = x4 + i - 1;
            if ((unsigned)xf >= (unsigned)(WW / 4)) continue;
#pragma unroll
            for (int j = 0; j < 3; j++) {
                int yy = y + j * 4 - 4;
                if ((unsigned)yy >= (unsigned)HH) continue;
                float w = wk[i * 3 + j];
                float4 v = img4[(size_t)yy * (WW / 4) + xf];
                acc.x += v.x * w; acc.y += v.y * w;
                acc.z += v.z * w; acc.w += v.w * w;
            }
        }
        out4[(size_t)y * (WW / 4) + x4] = acc;
    }
}

// ---------------------------------------------------------------------------
extern "C" void kernel_launch(void* const* d_in, const int* in_sizes, int n_in,
                              void* d_out, int out_size)
{
    const float* image = (const float*)d_in[0];
    const float* ctrl  = (const float*)d_in[1];
    const float* w1    = (const float*)d_in[2];
    const float* b1    = (const float*)d_in[3];
    const float* gamma = (const float*)d_in[4];
    const float* beta  = (const float*)d_in[5];
    const float* mean  = (const float*)d_in[6];
    const float* var   = (const float*)d_in[7];
    const float* w2    = (const float*)d_in[8];
    const float* b2    = (const float*)d_in[9];
    float* out = (float*)d_out;

    static int smem_set = 0;
    if (!smem_set) {
        cudaFuncSetAttribute(conv1_mma_kernel,
                             cudaFuncAttributeMaxDynamicSharedMemorySize, SMEM_TOTAL);
        smem_set = 1;
    }

    prep_w1_kernel<<<576, 256>>>(w1);
    conv1_mma_kernel<<<BB * NH, 256, SMEM_TOTAL>>>(ctrl, b1, gamma, beta, mean, var);
    conv2_kernel<<<dim3(NW / 32, NH / 16, BB), dim3(32, 8)>>>(w2, b2);
    translate_kernel<<<dim3(64, 6, BB), dim3(128, 2)>>>(image, out);
}

// round 6
// speedup vs baseline: 3.1936x; 1.6054x over previous
#include <cuda_runtime.h>
#include <cuda_fp16.h>
#include <cstdint>

#define BB 8
#define CC 128
#define NH 128
#define NW 128
#define C1 50
#define C2 18
#define HH 512
#define WW 512

// ---------------------------------------------------------------------------
// Device-global scratch (no allocations allowed)
// ---------------------------------------------------------------------------
// ctrl packed fp16 hi/lo: [b][chunk8][y][px][hi16|lo16]  (64B per (y,px))
__device__ __align__(16) __half g_ctrlp[(size_t)BB * 8 * NH * NW * 32];
// conv1 output packed fp16 hi/lo: [b][chunk4][y][px][hi16|lo16]
__device__ __align__(16) __half g_hp[(size_t)BB * 4 * NH * NW * 32];
__device__ float g_cond[(size_t)BB * C2 * NH * NW];
// conv1 weights fp16: [chunk8][tap9][oc64][cin16]
__device__ __align__(16) __half g_w1p[8 * 9 * 64 * 16];
// conv2 weights fp16: [chunk4][tap9][oc32][cin16]
__device__ __align__(16) __half g_w2p[4 * 9 * 32 * 16];

__device__ __forceinline__ uint32_t smem_u32(const void* p) {
    uint32_t a;
    asm("{ .reg .u64 t; cvta.to.shared.u64 t, %1; cvt.u32.u64 %0, t; }"
        : "=r"(a) : "l"(p));
    return a;
}

#define LDSM4(r, a)                                                            \
    asm volatile("ldmatrix.sync.aligned.m8n8.x4.shared.b16 {%0,%1,%2,%3}, [%4];" \
        : "=r"((r)[0]), "=r"((r)[1]), "=r"((r)[2]), "=r"((r)[3]) : "r"(a))

#define MMA16816(c, a, b0, b1)                                                 \
    asm volatile("mma.sync.aligned.m16n8k16.row.col.f32.f16.f16.f32 "          \
        "{%0,%1,%2,%3},{%4,%5,%6,%7},{%8,%9},{%0,%1,%2,%3};"                   \
        : "+f"((c)[0]), "+f"((c)[1]), "+f"((c)[2]), "+f"((c)[3])               \
        : "r"((a)[0]), "r"((a)[1]), "r"((a)[2]), "r"((a)[3]), "r"(b0), "r"(b1))

__device__ __forceinline__ uint32_t pack_h2(__half a, __half b) {
    return (uint32_t)__half_as_ushort(a) | ((uint32_t)__half_as_ushort(b) << 16);
}

// ---------------------------------------------------------------------------
// prep_ctrl: fp32 ctrl -> packed fp16 hi/lo [b][chunk][y][px][hi16|lo16]
// block = (b, chunk, y); 256 threads
// ---------------------------------------------------------------------------
__global__ __launch_bounds__(256) void prep_ctrl_kernel(const float* __restrict__ ctrl) {
    __shared__ float sm[16 * 132];
    const int bid = blockIdx.x;              // (b*8+chunk)*128+y
    const int y = bid & 127;
    const int bc = bid >> 7;
    const int chunk = bc & 7;
    const int b = bc >> 3;
    const int tid = threadIdx.x;

    const float* src = ctrl + (((size_t)b * CC + chunk * 16) * NH + y) * NW;
    for (int e = tid; e < 2048; e += 256) {
        int c = e >> 7, x = e & 127;
        sm[c * 132 + x] = src[(size_t)c * NH * NW + x];
    }
    __syncthreads();

    const int px = tid & 127, h = tid >> 7;  // h=0: hi, h=1: lo
    uint32_t u[8];
#pragma unroll
    for (int jp = 0; jp < 8; jp++) {
        __half o[2];
#pragma unroll
        for (int t = 0; t < 2; t++) {
            float v = sm[(2 * jp + t) * 132 + px];
            __half hi = __float2half(v);
            o[t] = h ? __float2half(v - __half2float(hi)) : hi;
        }
        u[jp] = pack_h2(o[0], o[1]);
    }
    float4* dst = ((float4*)g_ctrlp) + (((size_t)bid * 128 + px) * 4 + h * 2);
    dst[0] = make_float4(__uint_as_float(u[0]), __uint_as_float(u[1]),
                         __uint_as_float(u[2]), __uint_as_float(u[3]));
    dst[1] = make_float4(__uint_as_float(u[4]), __uint_as_float(u[5]),
                         __uint_as_float(u[6]), __uint_as_float(u[7]));
}

// ---------------------------------------------------------------------------
// prep_w1 / prep_w2: weights -> fp16 ldmatrix layout
// ---------------------------------------------------------------------------
__global__ void prep_w1_kernel(const float* __restrict__ w1) {
    int idx = blockIdx.x * 256 + threadIdx.x;
    if (idx >= 8 * 9 * 64 * 16) return;
    int jc = idx & 15;
    int oc = (idx >> 4) & 63;
    int r = idx >> 10;
    int tap = r % 9, chunk = r / 9;
    int dy = tap / 3, dx = tap % 3;
    float w = 0.f;
    if (oc < C1)
        w = w1[((oc * CC + chunk * 16 + jc) * 3 + dy) * 3 + dx];
    g_w1p[idx] = __float2half(w);
}

__global__ void prep_w2_kernel(const float* __restrict__ w2) {
    int idx = blockIdx.x * 256 + threadIdx.x;
    if (idx >= 4 * 9 * 32 * 16) return;
    int jc = idx & 15;
    int oc = (idx >> 4) & 31;
    int r = idx >> 9;
    int tap = r % 9, chunk = r / 9;
    int dy = tap / 3, dx = tap % 3;
    int cin = chunk * 16 + jc;
    float w = 0.f;
    if (oc < C2 && cin < C1)
        w = w2[((oc * C1 + cin) * 3 + dy) * 3 + dx];
    g_w2p[idx] = __float2half(w);
}

// ---------------------------------------------------------------------------
// conv1 mma: CTA = (b, y-pair). M=256 px (2 rows), N=64 oc, K=8 chunks x 9 taps x 16.
// A split fp16 hi/lo, B single fp16. Epilogue: bias/ReLU/BN -> packed g_hp.
// ---------------------------------------------------------------------------
#define C1_OFF_B 0
#define C1_B_REGION 3072                 // 64 rows * 48B
#define C1_OFF_A 27648                   // 9 * 3072
#define C1_A_H 24960                     // 4 rows * 130 px * 48B
#define C1_OFF_P 77568                   // params: 3 * 64 floats
#define C1_SMEM 78336

__global__ void __launch_bounds__(256, 2) conv1_mma_kernel(
    const float* __restrict__ b1, const float* __restrict__ gamma,
    const float* __restrict__ beta, const float* __restrict__ mean,
    const float* __restrict__ var)
{
    extern __shared__ char smem[];
    float* smemT = (float*)smem;                       // epilogue transpose (67,840B)
    float* smP = (float*)(smem + C1_OFF_P);            // [b1 64][s 64][bb 64]
    const uint32_t sb = smem_u32(smem);
    const int tid = threadIdx.x;
    const int lane = tid & 31;
    const int warp = tid >> 5;
    const int b = blockIdx.x >> 6;
    const int y0 = (blockIdx.x & 63) * 2;
    const int wpx = (warp >> 1) * 64;
    const int wn = (warp & 1) * 32;

    // params
    if (tid < 64) {
        float s = 0.f, bb = 0.f, b1v = 0.f;
        if (tid < C1) {
            s = gamma[tid] * rsqrtf(var[tid] + 1e-5f);
            bb = beta[tid] - mean[tid] * s;
            b1v = b1[tid];
        }
        smP[tid] = b1v; smP[64 + tid] = s; smP[128 + tid] = bb;
    }

    // per-lane ldmatrix addresses
    const int rA = (lane & 7) + ((lane >> 3) & 1) * 8;
    const int kbA = (lane >> 4) * 16;
    const int ocB = (lane & 7) + ((lane >> 4) << 3);
    const int kbB = ((lane >> 3) & 1) * 16;
    uint32_t aAddr[4];
#pragma unroll
    for (int mt = 0; mt < 4; mt++) {
        int p = wpx + mt * 16 + rA;
        aAddr[mt] = sb + C1_OFF_A + (uint32_t)((p >> 7) * 130 + (p & 127)) * 48 + kbA;
    }
    const uint32_t bAddr = sb + C1_OFF_B + (uint32_t)(wn + ocB) * 48 + kbB;

    float C[4][4][4];
#pragma unroll
    for (int i = 0; i < 4; i++)
#pragma unroll
        for (int j = 0; j < 4; j++)
#pragma unroll
            for (int k = 0; k < 4; k++) C[i][j][k] = 0.f;

    for (int chunk = 0; chunk < 8; chunk++) {
        __syncthreads();
        // stage B: 9 taps x 64 rows x 32B = 1152 float4
        {
            const float4* srcB = ((const float4*)g_w1p) + chunk * 1152;
            for (int e = tid; e < 1152; e += 256) {
                int r = e >> 1, q = e & 1;
                *(float4*)(smem + C1_OFF_B + (r >> 6) * C1_B_REGION + (r & 63) * 48 + q * 16) =
                    srcB[e];
            }
        }
        // stage A: 4 rows x 128 px x 64B = 2048 float4 (pure copies)
        {
            const float4* srcA = (const float4*)g_ctrlp;
            for (int e = tid; e < 2048; e += 256) {
                int s = e >> 9, x = (e >> 2) & 127, q = e & 3;
                int gy = y0 - 1 + s;
                float4 v = make_float4(0.f, 0.f, 0.f, 0.f);
                if ((unsigned)gy < NH)
                    v = srcA[(((size_t)(b * 8 + chunk) * 128 + gy) * 128 + x) * 4 + q];
                int h = q >> 1;
                *(float4*)(smem + C1_OFF_A + h * C1_A_H + (s * 130 + x + 1) * 48 + (q & 1) * 16) = v;
            }
            if (tid < 16) {  // halo cols 0,129 zero
                int s = tid & 3, h = (tid >> 2) & 1, col = (tid >> 3) ? 129 : 0;
                float4* p = (float4*)(smem + C1_OFF_A + h * C1_A_H + (s * 130 + col) * 48);
                p[0] = make_float4(0.f, 0.f, 0.f, 0.f);
                p[1] = make_float4(0.f, 0.f, 0.f, 0.f);
            }
        }
        __syncthreads();

#pragma unroll
        for (int dy = 0; dy < 3; dy++) {
#pragma unroll
            for (int dx = 0; dx < 3; dx++) {
                const int toff = (dy * 130 + dx) * 48;
                const int tap = dy * 3 + dx;
                uint32_t ah[16], al[16], bh[8];
#pragma unroll
                for (int mt = 0; mt < 4; mt++) LDSM4(ah + mt * 4, aAddr[mt] + toff);
#pragma unroll
                for (int mt = 0; mt < 4; mt++) LDSM4(al + mt * 4, aAddr[mt] + C1_A_H + toff);
                LDSM4(bh, bAddr + tap * C1_B_REGION);
                LDSM4(bh + 4, bAddr + tap * C1_B_REGION + 16 * 48);
#pragma unroll
                for (int mt = 0; mt < 4; mt++) {
#pragma unroll
                    for (int nt = 0; nt < 4; nt++) {
                        MMA16816(C[mt][nt], ah + mt * 4, bh[nt * 2], bh[nt * 2 + 1]);
                        MMA16816(C[mt][nt], al + mt * 4, bh[nt * 2], bh[nt * 2 + 1]);
                    }
                }
            }
        }
    }

    // epilogue: C -> smemT[oc][256 px] (stride 265), then pack g_hp
    __syncthreads();
    {
        const int g2 = lane >> 2, t4 = lane & 3;
#pragma unroll
        for (int mt = 0; mt < 4; mt++) {
#pragma unroll
            for (int nt = 0; nt < 4; nt++) {
                int px = wpx + mt * 16 + g2;
                int oc = wn + nt * 8 + t4 * 2;
                smemT[oc * 265 + px] = C[mt][nt][0];
                smemT[(oc + 1) * 265 + px] = C[mt][nt][1];
                smemT[oc * 265 + px + 8] = C[mt][nt][2];
                smemT[(oc + 1) * 265 + px + 8] = C[mt][nt][3];
            }
        }
    }
    __syncthreads();
    for (int e = tid; e < 1024; e += 256) {
        int c = e >> 8, px = e & 255;
        int gy = y0 + (px >> 7), x = px & 127;
        uint32_t uh[8], ul[8];
#pragma unroll
        for (int jp = 0; jp < 8; jp++) {
            __half oh[2], ol[2];
#pragma unroll
            for (int t = 0; t < 2; t++) {
                int j = 2 * jp + t;
                int oc = c * 16 + j;
                float val = 0.f;
                if (oc < C1) {
                    float acc = smemT[oc * 265 + px];
                    val = fmaxf(acc + smP[oc], 0.f) * smP[64 + oc] + smP[128 + oc];
                }
                __half hi = __float2half(val);
                oh[t] = hi;
                ol[t] = __float2half(val - __half2float(hi));
            }
            uh[jp] = pack_h2(oh[0], oh[1]);
            ul[jp] = pack_h2(ol[0], ol[1]);
        }
        float4* dst = ((float4*)g_hp) + (((size_t)(b * 4 + c) * 128 + gy) * 128 + x) * 4;
        dst[0] = make_float4(__uint_as_float(uh[0]), __uint_as_float(uh[1]),
                             __uint_as_float(uh[2]), __uint_as_float(uh[3]));
        dst[1] = make_float4(__uint_as_float(uh[4]), __uint_as_float(uh[5]),
                             __uint_as_float(uh[6]), __uint_as_float(uh[7]));
        dst[2] = make_float4(__uint_as_float(ul[0]), __uint_as_float(ul[1]),
                             __uint_as_float(ul[2]), __uint_as_float(ul[3]));
        dst[3] = make_float4(__uint_as_float(ul[4]), __uint_as_float(ul[5]),
                             __uint_as_float(ul[6]), __uint_as_float(ul[7]));
    }
}

// ---------------------------------------------------------------------------
// conv2 mma: CTA = (b, y-pair). M=256 px, N=32 oc (18 used), K=4 chunks x 9 taps x 16.
// ---------------------------------------------------------------------------
#define C2_OFF_B 0
#define C2_B_REGION 1536                 // 32 rows * 48B
#define C2_OFF_A 13824                   // 9 * 1536
#define C2_A_H 24960
#define C2_SMEM 63744                    // 13824 + 2*24960

__global__ void __launch_bounds__(256, 2) conv2_mma_kernel(const float* __restrict__ b2)
{
    extern __shared__ char smem[];
    float* smemT = (float*)smem;         // 32 x 260 floats = 33,280B
    const uint32_t sb = smem_u32(smem);
    const int tid = threadIdx.x;
    const int lane = tid & 31;
    const int warp = tid >> 5;
    const int b = blockIdx.x >> 6;
    const int y0 = (blockIdx.x & 63) * 2;
    const int wpx = warp * 32;

    const int rA = (lane & 7) + ((lane >> 3) & 1) * 8;
    const int kbA = (lane >> 4) * 16;
    const int ocB = (lane & 7) + ((lane >> 4) << 3);
    const int kbB = ((lane >> 3) & 1) * 16;
    uint32_t aAddr[2];
#pragma unroll
    for (int mt = 0; mt < 2; mt++) {
        int p = wpx + mt * 16 + rA;
        aAddr[mt] = sb + C2_OFF_A + (uint32_t)((p >> 7) * 130 + (p & 127)) * 48 + kbA;
    }
    const uint32_t bAddr = sb + C2_OFF_B + (uint32_t)ocB * 48 + kbB;

    float C[2][4][4];
#pragma unroll
    for (int i = 0; i < 2; i++)
#pragma unroll
        for (int j = 0; j < 4; j++)
#pragma unroll
            for (int k = 0; k < 4; k++) C[i][j][k] = 0.f;

    for (int chunk = 0; chunk < 4; chunk++) {
        __syncthreads();
        // stage B: 9 x 32 rows x 32B = 576 float4
        {
            const float4* srcB = ((const float4*)g_w2p) + chunk * 576;
            for (int e = tid; e < 576; e += 256) {
                int r = e >> 1, q = e & 1;
                *(float4*)(smem + C2_OFF_B + (r >> 5) * C2_B_REGION + (r & 31) * 48 + q * 16) =
                    srcB[e];
            }
        }
        // stage A from g_hp
        {
            const float4* srcA = (const float4*)g_hp;
            for (int e = tid; e < 2048; e += 256) {
                int s = e >> 9, x = (e >> 2) & 127, q = e & 3;
                int gy = y0 - 1 + s;
                float4 v = make_float4(0.f, 0.f, 0.f, 0.f);
                if ((unsigned)gy < NH)
                    v = srcA[(((size_t)(b * 4 + chunk) * 128 + gy) * 128 + x) * 4 + q];
                int h = q >> 1;
                *(float4*)(smem + C2_OFF_A + h * C2_A_H + (s * 130 + x + 1) * 48 + (q & 1) * 16) = v;
            }
            if (tid < 16) {
                int s = tid & 3, h = (tid >> 2) & 1, col = (tid >> 3) ? 129 : 0;
                float4* p = (float4*)(smem + C2_OFF_A + h * C2_A_H + (s * 130 + col) * 48);
                p[0] = make_float4(0.f, 0.f, 0.f, 0.f);
                p[1] = make_float4(0.f, 0.f, 0.f, 0.f);
            }
        }
        __syncthreads();

#pragma unroll
        for (int dy = 0; dy < 3; dy++) {
#pragma unroll
            for (int dx = 0; dx < 3; dx++) {
                const int toff = (dy * 130 + dx) * 48;
                const int tap = dy * 3 + dx;
                uint32_t ah[8], al[8], bh[8];
#pragma unroll
                for (int mt = 0; mt < 2; mt++) LDSM4(ah + mt * 4, aAddr[mt] + toff);
#pragma unroll
                for (int mt = 0; mt < 2; mt++) LDSM4(al + mt * 4, aAddr[mt] + C2_A_H + toff);
                LDSM4(bh, bAddr + tap * C2_B_REGION);
                LDSM4(bh + 4, bAddr + tap * C2_B_REGION + 16 * 48);
#pragma unroll
                for (int mt = 0; mt < 2; mt++) {
#pragma unroll
                    for (int nt = 0; nt < 4; nt++) {
                        MMA16816(C[mt][nt], ah + mt * 4, bh[nt * 2], bh[nt * 2 + 1]);
                        MMA16816(C[mt][nt], al + mt * 4, bh[nt * 2], bh[nt * 2 + 1]);
                    }
                }
            }
        }
    }

    // epilogue: C -> smemT[oc][256] (stride 260), +b2, fp32 stores
    __syncthreads();
    {
        const int g2 = lane >> 2, t4 = lane & 3;
#pragma unroll
        for (int mt = 0; mt < 2; mt++) {
#pragma unroll
            for (int nt = 0; nt < 4; nt++) {
                int px = wpx + mt * 16 + g2;
                int oc = nt * 8 + t4 * 2;
                smemT[oc * 260 + px] = C[mt][nt][0];
                smemT[(oc + 1) * 260 + px] = C[mt][nt][1];
                smemT[oc * 260 + px + 8] = C[mt][nt][2];
                smemT[(oc + 1) * 260 + px + 8] = C[mt][nt][3];
            }
        }
    }
    __syncthreads();
    for (int e = tid; e < C2 * 64; e += 256) {
        int oc = e >> 6, pq = e & 63;
        int px0 = pq * 4;
        int gy = y0 + (px0 >> 7), x = px0 & 127;
        float bv = b2[oc];
        float4 v = *(float4*)(smemT + oc * 260 + px0);
        v.x += bv; v.y += bv; v.z += bv; v.w += bv;
        *(float4*)(g_cond + (((size_t)b * C2 + oc) * NH + gy) * NW + x) = v;
    }
}

// ---------------------------------------------------------------------------
// translate (unchanged)
// ---------------------------------------------------------------------------
__global__ __launch_bounds__(256) void translate_kernel(
    const float* __restrict__ image, float* __restrict__ out)
{
    const int x4 = threadIdx.x;
    const int cellY = blockIdx.x * 2 + threadIdx.y;
    const int ch = blockIdx.y;
    const int b = blockIdx.z;
    const int g = ch / 3;

    float wk[9];
    const float* cond_b = g_cond + ((size_t)b * C2 + g * 9) * NH * NW;
#pragma unroll
    for (int k = 0; k < 9; k++)
        wk[k] = cond_b[(size_t)k * NH * NW + (size_t)cellY * NW + x4];

    const float4* img4 = (const float4*)image + (size_t)(b * 6 + ch) * HH * (WW / 4);
    float4* out4 = (float4*)out + (size_t)(b * 6 + ch) * HH * (WW / 4);

#pragma unroll
    for (int r = 0; r < 4; r++) {
        int y = cellY * 4 + r;
        float4 acc = make_float4(0.f, 0.f, 0.f, 0.f);
#pragma unroll
        for (int i = 0; i < 3; i++) {
            int xf = x4 + i - 1;
            if ((unsigned)xf >= (unsigned)(WW / 4)) continue;
#pragma unroll
            for (int j = 0; j < 3; j++) {
                int yy = y + j * 4 - 4;
                if ((unsigned)yy >= (unsigned)HH) continue;
                float w = wk[i * 3 + j];
                float4 v = img4[(size_t)yy * (WW / 4) + xf];
                acc.x += v.x * w; acc.y += v.y * w;
                acc.z += v.z * w; acc.w += v.w * w;
            }
        }
        out4[(size_t)y * (WW / 4) + x4] = acc;
    }
}

// ---------------------------------------------------------------------------
extern "C" void kernel_launch(void* const* d_in, const int* in_sizes, int n_in,
                              void* d_out, int out_size)
{
    const float* image = (const float*)d_in[0];
    const float* ctrl  = (const float*)d_in[1];
    const float* w1    = (const float*)d_in[2];
    const float* b1    = (const float*)d_in[3];
    const float* gamma = (const float*)d_in[4];
    const float* beta  = (const float*)d_in[5];
    const float* mean  = (const float*)d_in[6];
    const float* var   = (const float*)d_in[7];
    const float* w2    = (const float*)d_in[8];
    const float* b2    = (const float*)d_in[9];
    float* out = (float*)d_out;

    static int smem_set = 0;
    if (!smem_set) {
        cudaFuncSetAttribute(conv1_mma_kernel,
                             cudaFuncAttributeMaxDynamicSharedMemorySize, C1_SMEM);
        cudaFuncSetAttribute(conv2_mma_kernel,
                             cudaFuncAttributeMaxDynamicSharedMemorySize, C2_SMEM);
        smem_set = 1;
    }

    prep_ctrl_kernel<<<BB * 8 * NH, 256>>>(ctrl);
    prep_w1_kernel<<<288, 256>>>(w1);
    prep_w2_kernel<<<72, 256>>>(w2);
    conv1_mma_kernel<<<BB * 64, 256, C1_SMEM>>>(b1, gamma, beta, mean, var);
    conv2_mma_kernel<<<BB * 64, 256, C2_SMEM>>>(b2);
    translate_kernel<<<dim3(64, 6, BB), dim3(128, 2)>>>(image, out);
}

// round 7
// speedup vs baseline: 3.3316x; 1.0432x over previous
#include <cuda_runtime.h>
#include <cuda_fp16.h>
#include <cstdint>

#define BB 8
#define CC 128
#define NH 128
#define NW 128
#define C1 50
#define C2 18
#define HH 512
#define WW 512

// ---------------------------------------------------------------------------
// Device-global scratch
// ---------------------------------------------------------------------------
// ctrl packed fp16 hi/lo: [b][chunk8][y][x][h2][q2] (16B units, 64B per (y,x))
__device__ __align__(16) __half g_ctrlp[(size_t)BB * 8 * NH * NW * 32];
// conv1 output packed fp16 hi/lo: [b][chunk4][y][x][h2][q2]
__device__ __align__(16) __half g_hp[(size_t)BB * 4 * NH * NW * 32];
__device__ float g_cond[(size_t)BB * C2 * NH * NW];
// conv1 weights fp16, PRE-SWIZZLED smem image: [chunk8][tap9][oc64][q2-swz][8]
__device__ __align__(16) __half g_w1p[8 * 9 * 64 * 16];
// conv2 weights fp16, PRE-SWIZZLED: [chunk4][tap9][oc32][q2-swz][8]
__device__ __align__(16) __half g_w2p[4 * 9 * 32 * 16];

__device__ __forceinline__ uint32_t smem_u32(const void* p) {
    uint32_t a;
    asm("{ .reg .u64 t; cvta.to.shared.u64 t, %1; cvt.u32.u64 %0, t; }"
        : "=r"(a) : "l"(p));
    return a;
}

#define LDSM4(r, a)                                                            \
    asm volatile("ldmatrix.sync.aligned.m8n8.x4.shared.b16 {%0,%1,%2,%3}, [%4];" \
        : "=r"((r)[0]), "=r"((r)[1]), "=r"((r)[2]), "=r"((r)[3]) : "r"(a))

#define MMA16816(c, a, b0, b1)                                                 \
    asm volatile("mma.sync.aligned.m16n8k16.row.col.f32.f16.f16.f32 "          \
        "{%0,%1,%2,%3},{%4,%5,%6,%7},{%8,%9},{%0,%1,%2,%3};"                   \
        : "+f"((c)[0]), "+f"((c)[1]), "+f"((c)[2]), "+f"((c)[3])               \
        : "r"((a)[0]), "r"((a)[1]), "r"((a)[2]), "r"((a)[3]), "r"(b0), "r"(b1))

#define CPA16(dst, src, sz)                                                    \
    asm volatile("cp.async.cg.shared.global [%0], [%1], 16, %2;"               \
        :: "r"(dst), "l"(src), "r"(sz) : "memory")
#define CP_COMMIT() asm volatile("cp.async.commit_group;" ::: "memory")
#define CP_WAIT1()  asm volatile("cp.async.wait_group 1;" ::: "memory")
#define CP_WAIT0()  asm volatile("cp.async.wait_group 0;" ::: "memory")

__device__ __forceinline__ uint32_t pack_h2(__half a, __half b) {
    return (uint32_t)__half_as_ushort(a) | ((uint32_t)__half_as_ushort(b) << 16);
}

// ---------------------------------------------------------------------------
// prep_ctrl: fp32 ctrl -> packed fp16 hi/lo (unchanged layout)
// ---------------------------------------------------------------------------
__global__ __launch_bounds__(256) void prep_ctrl_kernel(const float* __restrict__ ctrl) {
    __shared__ float sm[16 * 132];
    const int bid = blockIdx.x;
    const int y = bid & 127;
    const int bc = bid >> 7;
    const int chunk = bc & 7;
    const int b = bc >> 3;
    const int tid = threadIdx.x;

    const float* src = ctrl + (((size_t)b * CC + chunk * 16) * NH + y) * NW;
    for (int e = tid; e < 2048; e += 256) {
        int c = e >> 7, x = e & 127;
        sm[c * 132 + x] = src[(size_t)c * NH * NW + x];
    }
    __syncthreads();

    const int px = tid & 127, h = tid >> 7;
    uint32_t u[8];
#pragma unroll
    for (int jp = 0; jp < 8; jp++) {
        __half o[2];
#pragma unroll
        for (int t = 0; t < 2; t++) {
            float v = sm[(2 * jp + t) * 132 + px];
            __half hi = __float2half(v);
            o[t] = h ? __float2half(v - __half2float(hi)) : hi;
        }
        u[jp] = pack_h2(o[0], o[1]);
    }
    float4* dst = ((float4*)g_ctrlp) + (((size_t)bid * 128 + px) * 4 + h * 2);
    dst[0] = make_float4(__uint_as_float(u[0]), __uint_as_float(u[1]),
                         __uint_as_float(u[2]), __uint_as_float(u[3]));
    dst[1] = make_float4(__uint_as_float(u[4]), __uint_as_float(u[5]),
                         __uint_as_float(u[6]), __uint_as_float(u[7]));
}

// ---------------------------------------------------------------------------
// prep weights: fp16, pre-swizzled (q ^= (oc>>2)&1) so staging is linear copy
// ---------------------------------------------------------------------------
__global__ void prep_w1_kernel(const float* __restrict__ w1) {
    int idx = blockIdx.x * 256 + threadIdx.x;
    if (idx >= 8 * 9 * 64 * 16) return;
    int jc = idx & 15;
    int oc = (idx >> 4) & 63;
    int r = idx >> 10;
    int tap = r % 9, chunk = r / 9;
    int dy = tap / 3, dx = tap % 3;
    float w = 0.f;
    if (oc < C1)
        w = w1[((oc * CC + chunk * 16 + jc) * 3 + dy) * 3 + dx];
    int q = (jc >> 3) ^ ((oc >> 2) & 1);
    g_w1p[((chunk * 9 + tap) * 64 + oc) * 16 + q * 8 + (jc & 7)] = __float2half(w);
}

__global__ void prep_w2_kernel(const float* __restrict__ w2) {
    int idx = blockIdx.x * 256 + threadIdx.x;
    if (idx >= 4 * 9 * 32 * 16) return;
    int jc = idx & 15;
    int oc = (idx >> 4) & 31;
    int r = idx >> 9;
    int tap = r % 9, chunk = r / 9;
    int dy = tap / 3, dx = tap % 3;
    int cin = chunk * 16 + jc;
    float w = 0.f;
    if (oc < C2 && cin < C1)
        w = w2[((oc * C1 + cin) * 3 + dy) * 3 + dx];
    int q = (jc >> 3) ^ ((oc >> 2) & 1);
    g_w2p[((chunk * 9 + tap) * 32 + oc) * 16 + q * 8 + (jc & 7)] = __float2half(w);
}

// ---------------------------------------------------------------------------
// conv1 mma, cp.async double-buffered, XOR-swizzled 32B rows.
// CTA = (b, y-pair). M=256 px, N=64 oc, K=8 chunks x 9 taps x 16.
// smem: A bufs 2 x [h2][520 rows x 32B]  = 66,560
//       B bufs 2 x [tap9][oc64 x 32B]    = 36,864  (offset 66,560)
//       params 3x64 floats at 103,424;  total 104,192
// ---------------------------------------------------------------------------
#define C1_A_H 16640
#define C1_A_BUF 33280
#define C1_OFF_B 66560
#define C1_B_BUF 18432
#define C1_OFF_P 103424
#define C1_SMEM 104192

__global__ void __launch_bounds__(256, 2) conv1_mma_kernel(
    const float* __restrict__ b1, const float* __restrict__ gamma,
    const float* __restrict__ beta, const float* __restrict__ mean,
    const float* __restrict__ var)
{
    extern __shared__ char smem[];
    float* smemT = (float*)smem;
    float* smP = (float*)(smem + C1_OFF_P);
    const uint32_t sb = smem_u32(smem);
    const int tid = threadIdx.x;
    const int lane = tid & 31;
    const int warp = tid >> 5;
    const int b = blockIdx.x >> 6;
    const int y0 = (blockIdx.x & 63) * 2;
    const int wpx = (warp >> 1) * 64;
    const int wn = (warp & 1) * 32;

    if (tid < 64) {
        float s = 0.f, bb = 0.f, b1v = 0.f;
        if (tid < C1) {
            s = gamma[tid] * rsqrtf(var[tid] + 1e-5f);
            bb = beta[tid] - mean[tid] * s;
            b1v = b1[tid];
        }
        smP[tid] = b1v; smP[64 + tid] = s; smP[128 + tid] = bb;
    }
    // zero halo columns (both buffers, both h): positions s*130+0 and s*130+129
    if (tid < 64) {
        int q = tid & 1, col = (tid >> 1) & 1, s = (tid >> 2) & 3;
        int h = (tid >> 4) & 1, d = tid >> 5;
        int ri = s * 130 + (col ? 129 : 0);
        *(float4*)(smem + d * C1_A_BUF + h * C1_A_H + ri * 32 + q * 16) =
            make_float4(0.f, 0.f, 0.f, 0.f);
    }

    // ldmatrix per-lane bases
    const int rA = (lane & 7) + ((lane >> 3) & 1) * 8;
    const int qA = lane >> 4;
    int riA[4];
#pragma unroll
    for (int mt = 0; mt < 4; mt++) {
        int px = wpx + mt * 16 + rA;
        riA[mt] = (px >> 7) * 130 + (px & 127);
    }
    const int ocB = (lane & 7) + ((lane >> 4) << 3);
    const int qB = (lane >> 3) & 1;
    const int ocRow = wn + ocB;
    const uint32_t bSwz =
        sb + C1_OFF_B + (uint32_t)ocRow * 32 + (uint32_t)((qB ^ (ocRow >> 2)) & 1) * 16;

    float C[4][4][4];
#pragma unroll
    for (int i = 0; i < 4; i++)
#pragma unroll
        for (int j = 0; j < 4; j++)
#pragma unroll
            for (int k = 0; k < 4; k++) C[i][j][k] = 0.f;

    const char* ctrlBase = (const char*)g_ctrlp;
    const char* wBase = (const char*)g_w1p;

    // stage chunk c into buffer d
    auto stage = [&](int c, int d) {
        const char* srcA = ctrlBase + (size_t)(b * 8 + c) * (128 * 128 * 64);
        uint32_t aB = sb + d * C1_A_BUF;
#pragma unroll
        for (int it = 0; it < 8; it++) {
            int e = tid + it * 256;
            int s = e >> 9, r5 = e & 511;
            int x = r5 >> 2, h = (r5 >> 1) & 1, q = r5 & 1;
            int gy = y0 - 1 + s;
            int gyc = gy < 0 ? 0 : (gy > 127 ? 127 : gy);
            const char* src = srcA + ((size_t)gyc * 128 + x) * 64 + h * 32 + q * 16;
            int ri = s * 130 + x + 1;
            uint32_t dst = aB + h * C1_A_H + ri * 32 + ((q ^ (ri >> 2)) & 1) * 16;
            CPA16(dst, src, ((unsigned)gy < 128u) ? 16 : 0);
        }
        uint32_t bBf = sb + C1_OFF_B + d * C1_B_BUF;
        const char* srcB = wBase + (size_t)c * C1_B_BUF;
        for (int e = tid; e < 1152; e += 256)
            CPA16(bBf + e * 16, srcB + e * 16, 16);
        CP_COMMIT();
    };

    stage(0, 0);
    for (int c = 0; c < 8; c++) {
        if (c < 7) { stage(c + 1, (c + 1) & 1); CP_WAIT1(); }
        else CP_WAIT0();
        __syncthreads();

        const uint32_t aBuf = sb + (c & 1) * C1_A_BUF;
        const uint32_t bBuf = bSwz + (c & 1) * C1_B_BUF;
#pragma unroll
        for (int dy = 0; dy < 3; dy++) {
#pragma unroll
            for (int dx = 0; dx < 3; dx++) {
                const int tap = dy * 3 + dx;
                uint32_t bh[8];
                uint32_t bt = bBuf + tap * 2048;
                LDSM4(bh, bt);
                LDSM4(bh + 4, bt + 512);
#pragma unroll
                for (int h = 0; h < 2; h++) {
                    uint32_t a[16];
#pragma unroll
                    for (int mt = 0; mt < 4; mt++) {
                        int rt = riA[mt] + dy * 130 + dx;
                        uint32_t ad = aBuf + h * C1_A_H + rt * 32 +
                                      ((qA ^ (rt >> 2)) & 1) * 16;
                        LDSM4(a + mt * 4, ad);
                    }
#pragma unroll
                    for (int mt = 0; mt < 4; mt++)
#pragma unroll
                        for (int nt = 0; nt < 4; nt++)
                            MMA16816(C[mt][nt], a + mt * 4, bh[nt * 2], bh[nt * 2 + 1]);
                }
            }
        }
        __syncthreads();
    }

    // epilogue: C -> smemT[oc][256 px] stride 265, then bias/ReLU/BN -> packed g_hp
    {
        const int g2 = lane >> 2, t4 = lane & 3;
#pragma unroll
        for (int mt = 0; mt < 4; mt++) {
#pragma unroll
            for (int nt = 0; nt < 4; nt++) {
                int px = wpx + mt * 16 + g2;
                int oc = wn + nt * 8 + t4 * 2;
                smemT[oc * 265 + px] = C[mt][nt][0];
                smemT[(oc + 1) * 265 + px] = C[mt][nt][1];
                smemT[oc * 265 + px + 8] = C[mt][nt][2];
                smemT[(oc + 1) * 265 + px + 8] = C[mt][nt][3];
            }
        }
    }
    __syncthreads();
    for (int e = tid; e < 1024; e += 256) {
        int c = e >> 8, px = e & 255;
        int gy = y0 + (px >> 7), x = px & 127;
        uint32_t uh[8], ul[8];
#pragma unroll
        for (int jp = 0; jp < 8; jp++) {
            __half oh[2], ol[2];
#pragma unroll
            for (int t = 0; t < 2; t++) {
                int oc = c * 16 + 2 * jp + t;
                float val = 0.f;
                if (oc < C1) {
                    float acc = smemT[oc * 265 + px];
                    val = fmaxf(acc + smP[oc], 0.f) * smP[64 + oc] + smP[128 + oc];
                }
                __half hi = __float2half(val);
                oh[t] = hi;
                ol[t] = __float2half(val - __half2float(hi));
            }
            uh[jp] = pack_h2(oh[0], oh[1]);
            ul[jp] = pack_h2(ol[0], ol[1]);
        }
        float4* dst = ((float4*)g_hp) + (((size_t)(b * 4 + c) * 128 + gy) * 128 + x) * 4;
        dst[0] = make_float4(__uint_as_float(uh[0]), __uint_as_float(uh[1]),
                             __uint_as_float(uh[2]), __uint_as_float(uh[3]));
        dst[1] = make_float4(__uint_as_float(uh[4]), __uint_as_float(uh[5]),
                             __uint_as_float(uh[6]), __uint_as_float(uh[7]));
        dst[2] = make_float4(__uint_as_float(ul[0]), __uint_as_float(ul[1]),
                             __uint_as_float(ul[2]), __uint_as_float(ul[3]));
        dst[3] = make_float4(__uint_as_float(ul[4]), __uint_as_float(ul[5]),
                             __uint_as_float(ul[6]), __uint_as_float(ul[7]));
    }
}

// ---------------------------------------------------------------------------
// conv2 mma: same scheme. M=256 px, N=32 (18 used), K=4 chunks x 9 taps x 16.
// smem: A 2 x 33,280 = 66,560;  B 2 x 9,216 = 18,432 (offset 66,560); total 84,992
// ---------------------------------------------------------------------------
#define C2_OFF_B 66560
#define C2_B_BUF 9216
#define C2_SMEM 84992

__global__ void __launch_bounds__(256, 2) conv2_mma_kernel(const float* __restrict__ b2)
{
    extern __shared__ char smem[];
    float* smemT = (float*)smem;
    const uint32_t sb = smem_u32(smem);
    const int tid = threadIdx.x;
    const int lane = tid & 31;
    const int warp = tid >> 5;
    const int b = blockIdx.x >> 6;
    const int y0 = (blockIdx.x & 63) * 2;
    const int wpx = warp * 32;

    if (tid < 64) {
        int q = tid & 1, col = (tid >> 1) & 1, s = (tid >> 2) & 3;
        int h = (tid >> 4) & 1, d = tid >> 5;
        int ri = s * 130 + (col ? 129 : 0);
        *(float4*)(smem + d * C1_A_BUF + h * C1_A_H + ri * 32 + q * 16) =
            make_float4(0.f, 0.f, 0.f, 0.f);
    }

    const int rA = (lane & 7) + ((lane >> 3) & 1) * 8;
    const int qA = lane >> 4;
    int riA[2];
#pragma unroll
    for (int mt = 0; mt < 2; mt++) {
        int px = wpx + mt * 16 + rA;
        riA[mt] = (px >> 7) * 130 + (px & 127);
    }
    const int ocB = (lane & 7) + ((lane >> 4) << 3);
    const int qB = (lane >> 3) & 1;
    const uint32_t bSwz =
        sb + C2_OFF_B + (uint32_t)ocB * 32 + (uint32_t)((qB ^ (ocB >> 2)) & 1) * 16;

    float C[2][4][4];
#pragma unroll
    for (int i = 0; i < 2; i++)
#pragma unroll
        for (int j = 0; j < 4; j++)
#pragma unroll
            for (int k = 0; k < 4; k++) C[i][j][k] = 0.f;

    const char* hpBase = (const char*)g_hp;
    const char* wBase = (const char*)g_w2p;

    auto stage = [&](int c, int d) {
        const char* srcA = hpBase + (size_t)(b * 4 + c) * (128 * 128 * 64);
        uint32_t aB = sb + d * C1_A_BUF;
#pragma unroll
        for (int it = 0; it < 8; it++) {
            int e = tid + it * 256;
            int s = e >> 9, r5 = e & 511;
            int x = r5 >> 2, h = (r5 >> 1) & 1, q = r5 & 1;
            int gy = y0 - 1 + s;
            int gyc = gy < 0 ? 0 : (gy > 127 ? 127 : gy);
            const char* src = srcA + ((size_t)gyc * 128 + x) * 64 + h * 32 + q * 16;
            int ri = s * 130 + x + 1;
            uint32_t dst = aB + h * C1_A_H + ri * 32 + ((q ^ (ri >> 2)) & 1) * 16;
            CPA16(dst, src, ((unsigned)gy < 128u) ? 16 : 0);
        }
        uint32_t bBf = sb + C2_OFF_B + d * C2_B_BUF;
        const char* srcB = wBase + (size_t)c * C2_B_BUF;
        for (int e = tid; e < 576; e += 256)
            CPA16(bBf + e * 16, srcB + e * 16, 16);
        CP_COMMIT();
    };

    stage(0, 0);
    for (int c = 0; c < 4; c++) {
        if (c < 3) { stage(c + 1, (c + 1) & 1); CP_WAIT1(); }
        else CP_WAIT0();
        __syncthreads();

        const uint32_t aBuf = sb + (c & 1) * C1_A_BUF;
        const uint32_t bBuf = bSwz + (c & 1) * C2_B_BUF;
#pragma unroll
        for (int dy = 0; dy < 3; dy++) {
#pragma unroll
            for (int dx = 0; dx < 3; dx++) {
                const int tap = dy * 3 + dx;
                uint32_t bh[8];
                uint32_t bt = bBuf + tap * 1024;
                LDSM4(bh, bt);
                LDSM4(bh + 4, bt + 512);
#pragma unroll
                for (int h = 0; h < 2; h++) {
                    uint32_t a[8];
#pragma unroll
                    for (int mt = 0; mt < 2; mt++) {
                        int rt = riA[mt] + dy * 130 + dx;
                        uint32_t ad = aBuf + h * C1_A_H + rt * 32 +
                                      ((qA ^ (rt >> 2)) & 1) * 16;
                        LDSM4(a + mt * 4, ad);
                    }
#pragma unroll
                    for (int mt = 0; mt < 2; mt++)
#pragma unroll
                        for (int nt = 0; nt < 4; nt++)
                            MMA16816(C[mt][nt], a + mt * 4, bh[nt * 2], bh[nt * 2 + 1]);
                }
            }
        }
        __syncthreads();
    }

    // epilogue: smemT[oc][256] stride 260, +b2, fp32 stores
    {
        const int g2 = lane >> 2, t4 = lane & 3;
#pragma unroll
        for (int mt = 0; mt < 2; mt++) {
#pragma unroll
            for (int nt = 0; nt < 4; nt++) {
                int px = wpx + mt * 16 + g2;
                int oc = nt * 8 + t4 * 2;
                smemT[oc * 260 + px] = C[mt][nt][0];
                smemT[(oc + 1) * 260 + px] = C[mt][nt][1];
                smemT[oc * 260 + px + 8] = C[mt][nt][2];
                smemT[(oc + 1) * 260 + px + 8] = C[mt][nt][3];
            }
        }
    }
    __syncthreads();
    for (int e = tid; e < C2 * 64; e += 256) {
        int oc = e >> 6, pq = e & 63;
        int px0 = pq * 4;
        int gy = y0 + (px0 >> 7), x = px0 & 127;
        float bv = b2[oc];
        float4 v = *(float4*)(smemT + oc * 260 + px0);
        v.x += bv; v.y += bv; v.z += bv; v.w += bv;
        *(float4*)(g_cond + (((size_t)b * C2 + oc) * NH + gy) * NW + x) = v;
    }
}

// ---------------------------------------------------------------------------
// translate (unchanged)
// ---------------------------------------------------------------------------
__global__ __launch_bounds__(256) void translate_kernel(
    const float* __restrict__ image, float* __restrict__ out)
{
    const int x4 = threadIdx.x;
    const int cellY = blockIdx.x * 2 + threadIdx.y;
    const int ch = blockIdx.y;
    const int b = blockIdx.z;
    const int g = ch / 3;

    float wk[9];
    const float* cond_b = g_cond + ((size_t)b * C2 + g * 9) * NH * NW;
#pragma unroll
    for (int k = 0; k < 9; k++)
        wk[k] = cond_b[(size_t)k * NH * NW + (size_t)cellY * NW + x4];

    const float4* img4 = (const float4*)image + (size_t)(b * 6 + ch) * HH * (WW / 4);
    float4* out4 = (float4*)out + (size_t)(b * 6 + ch) * HH * (WW / 4);

#pragma unroll
    for (int r = 0; r < 4; r++) {
        int y = cellY * 4 + r;
        float4 acc = make_float4(0.f, 0.f, 0.f, 0.f);
#pragma unroll
        for (int i = 0; i < 3; i++) {
            int xf = x4 + i - 1;
            if ((unsigned)xf >= (unsigned)(WW / 4)) continue;
#pragma unroll
            for (int j = 0; j < 3; j++) {
                int yy = y + j * 4 - 4;
                if ((unsigned)yy >= (unsigned)HH) continue;
                float w = wk[i * 3 + j];
                float4 v = img4[(size_t)yy * (WW / 4) + xf];
                acc.x += v.x * w; acc.y += v.y * w;
                acc.z += v.z * w; acc.w += v.w * w;
            }
        }
        out4[(size_t)y * (WW / 4) + x4] = acc;
    }
}

// ---------------------------------------------------------------------------
extern "C" void kernel_launch(void* const* d_in, const int* in_sizes, int n_in,
                              void* d_out, int out_size)
{
    const float* image = (const float*)d_in[0];
    const float* ctrl  = (const float*)d_in[1];
    const float* w1    = (const float*)d_in[2];
    const float* b1    = (const float*)d_in[3];
    const float* gamma = (const float*)d_in[4];
    const float* beta  = (const float*)d_in[5];
    const float* mean  = (const float*)d_in[6];
    const float* var   = (const float*)d_in[7];
    const float* w2    = (const float*)d_in[8];
    const float* b2    = (const float*)d_in[9];
    float* out = (float*)d_out;

    static int smem_set = 0;
    if (!smem_set) {
        cudaFuncSetAttribute(conv1_mma_kernel,
                             cudaFuncAttributeMaxDynamicSharedMemorySize, C1_SMEM);
        cudaFuncSetAttribute(conv2_mma_kernel,
                             cudaFuncAttributeMaxDynamicSharedMemorySize, C2_SMEM);
        smem_set = 1;
    }

    prep_ctrl_kernel<<<BB * 8 * NH, 256>>>(ctrl);
    prep_w1_kernel<<<288, 256>>>(w1);
    prep_w2_kernel<<<72, 256>>>(w2);
    conv1_mma_kernel<<<BB * 64, 256, C1_SMEM>>>(b1, gamma, beta, mean, var);
    conv2_mma_kernel<<<BB * 64, 256, C2_SMEM>>>(b2);
    translate_kernel<<<dim3(64, 6, BB), dim3(128, 2)>>>(image, out);
}

// round 8
// speedup vs baseline: 4.6349x; 1.3912x over previous
#include <cuda_runtime.h>
#include <cuda_fp16.h>
#include <cstdint>

#define BB 8
#define CC 128
#define NH 128
#define NW 128
#define C1 50
#define C2 18
#define HH 512
#define WW 512

// ---------------------------------------------------------------------------
// Device-global scratch
// ---------------------------------------------------------------------------
// ctrl fp16: [b][chunk8][y][x][q2] (16B units, 32B per (y,x))
__device__ __align__(16) __half g_ctrlp[(size_t)BB * 8 * NH * NW * 16];
// conv1 output fp16: [b][chunk4][y][x][q2]
__device__ __align__(16) __half g_hp[(size_t)BB * 4 * NH * NW * 16];
__device__ float g_cond[(size_t)BB * C2 * NH * NW];
// conv1 weights fp16, pre-swizzled: [chunk8][tap9][oc64][q2-swz][8]
__device__ __align__(16) __half g_w1p[8 * 9 * 64 * 16];
// conv2 weights fp16, pre-swizzled: [chunk4][tap9][oc32][q2-swz][8]
__device__ __align__(16) __half g_w2p[4 * 9 * 32 * 16];

__device__ __forceinline__ uint32_t smem_u32(const void* p) {
    uint32_t a;
    asm("{ .reg .u64 t; cvta.to.shared.u64 t, %1; cvt.u32.u64 %0, t; }"
        : "=r"(a) : "l"(p));
    return a;
}

#define LDSM4(r, a)                                                            \
    asm volatile("ldmatrix.sync.aligned.m8n8.x4.shared.b16 {%0,%1,%2,%3}, [%4];" \
        : "=r"((r)[0]), "=r"((r)[1]), "=r"((r)[2]), "=r"((r)[3]) : "r"(a))

#define MMA16816(c, a, b0, b1)                                                 \
    asm volatile("mma.sync.aligned.m16n8k16.row.col.f32.f16.f16.f32 "          \
        "{%0,%1,%2,%3},{%4,%5,%6,%7},{%8,%9},{%0,%1,%2,%3};"                   \
        : "+f"((c)[0]), "+f"((c)[1]), "+f"((c)[2]), "+f"((c)[3])               \
        : "r"((a)[0]), "r"((a)[1]), "r"((a)[2]), "r"((a)[3]), "r"(b0), "r"(b1))

#define CPA16(dst, src, sz)                                                    \
    asm volatile("cp.async.cg.shared.global [%0], [%1], 16, %2;"               \
        :: "r"(dst), "l"(src), "r"(sz) : "memory")
#define CP_COMMIT() asm volatile("cp.async.commit_group;" ::: "memory")
#define CP_WAIT1()  asm volatile("cp.async.wait_group 1;" ::: "memory")
#define CP_WAIT0()  asm volatile("cp.async.wait_group 0;" ::: "memory")

__device__ __forceinline__ uint32_t pack_h2(__half a, __half b) {
    return (uint32_t)__half_as_ushort(a) | ((uint32_t)__half_as_ushort(b) << 16);
}

// ---------------------------------------------------------------------------
// prep_ctrl: fp32 ctrl -> fp16 [b][chunk][y][x][q2]
// ---------------------------------------------------------------------------
__global__ __launch_bounds__(256) void prep_ctrl_kernel(const float* __restrict__ ctrl) {
    __shared__ float sm[16 * 132];
    const int bid = blockIdx.x;              // (b*8+chunk)*128+y
    const int y = bid & 127;
    const int bc = bid >> 7;
    const int chunk = bc & 7;
    const int b = bc >> 3;
    const int tid = threadIdx.x;

    const float* src = ctrl + (((size_t)b * CC + chunk * 16) * NH + y) * NW;
    for (int e = tid; e < 2048; e += 256) {
        int c = e >> 7, x = e & 127;
        sm[c * 132 + x] = src[(size_t)c * NH * NW + x];
    }
    __syncthreads();

    const int px = tid & 127, q = tid >> 7;  // q: cin half (0..7 / 8..15)
    uint32_t u[4];
#pragma unroll
    for (int jp = 0; jp < 4; jp++) {
        __half o[2];
#pragma unroll
        for (int t = 0; t < 2; t++) {
            float v = sm[(q * 8 + 2 * jp + t) * 132 + px];
            o[t] = __float2half(v);
        }
        u[jp] = pack_h2(o[0], o[1]);
    }
    float4* dst = ((float4*)g_ctrlp) + (((size_t)bid * 128 + px) * 2 + q);
    dst[0] = make_float4(__uint_as_float(u[0]), __uint_as_float(u[1]),
                         __uint_as_float(u[2]), __uint_as_float(u[3]));
}

// ---------------------------------------------------------------------------
// prep weights: fp16, pre-swizzled (q ^= (oc>>2)&1)
// ---------------------------------------------------------------------------
__global__ void prep_w1_kernel(const float* __restrict__ w1) {
    int idx = blockIdx.x * 256 + threadIdx.x;
    if (idx >= 8 * 9 * 64 * 16) return;
    int jc = idx & 15;
    int oc = (idx >> 4) & 63;
    int r = idx >> 10;
    int tap = r % 9, chunk = r / 9;
    int dy = tap / 3, dx = tap % 3;
    float w = 0.f;
    if (oc < C1)
        w = w1[((oc * CC + chunk * 16 + jc) * 3 + dy) * 3 + dx];
    int q = (jc >> 3) ^ ((oc >> 2) & 1);
    g_w1p[((chunk * 9 + tap) * 64 + oc) * 16 + q * 8 + (jc & 7)] = __float2half(w);
}

__global__ void prep_w2_kernel(const float* __restrict__ w2) {
    int idx = blockIdx.x * 256 + threadIdx.x;
    if (idx >= 4 * 9 * 32 * 16) return;
    int jc = idx & 15;
    int oc = (idx >> 4) & 31;
    int r = idx >> 9;
    int tap = r % 9, chunk = r / 9;
    int dy = tap / 3, dx = tap % 3;
    int cin = chunk * 16 + jc;
    float w = 0.f;
    if (oc < C2 && cin < C1)
        w = w2[((oc * C1 + cin) * 3 + dy) * 3 + dx];
    int q = (jc >> 3) ^ ((oc >> 2) & 1);
    g_w2p[((chunk * 9 + tap) * 32 + oc) * 16 + q * 8 + (jc & 7)] = __float2half(w);
}

// ---------------------------------------------------------------------------
// conv1 mma, single fp16, cp.async double-buffered, XOR-swizzled 32B rows.
// CTA = (b, y-pair). M=256 px, N=64 oc, K=8 chunks x 9 taps x 16.
// smem: A 2 x 16,640 = 33,280; B 2 x 18,432 = 36,864 @33,280; P @70,144
// ---------------------------------------------------------------------------
#define C1_A_BUF 16640
#define C1_OFF_B 33280
#define C1_B_BUF 18432
#define C1_OFF_P 70144
#define C1_SMEM 70912

__global__ void __launch_bounds__(256, 2) conv1_mma_kernel(
    const float* __restrict__ b1, const float* __restrict__ gamma,
    const float* __restrict__ beta, const float* __restrict__ mean,
    const float* __restrict__ var)
{
    extern __shared__ char smem[];
    float* smemT = (float*)smem;
    float* smP = (float*)(smem + C1_OFF_P);
    const uint32_t sb = smem_u32(smem);
    const int tid = threadIdx.x;
    const int lane = tid & 31;
    const int warp = tid >> 5;
    const int b = blockIdx.x >> 6;
    const int y0 = (blockIdx.x & 63) * 2;
    const int wpx = (warp >> 1) * 64;
    const int wn = (warp & 1) * 32;

    if (tid < 64) {
        float s = 0.f, bb = 0.f, b1v = 0.f;
        if (tid < C1) {
            s = gamma[tid] * rsqrtf(var[tid] + 1e-5f);
            bb = beta[tid] - mean[tid] * s;
            b1v = b1[tid];
        }
        smP[tid] = b1v; smP[64 + tid] = s; smP[128 + tid] = bb;
    }
    // zero halo columns: ri = s*130 + {0,129}, both buffers, both q
    if (tid < 32) {
        int q = tid & 1, col = (tid >> 1) & 1, s = (tid >> 2) & 3, d = (tid >> 4) & 1;
        int ri = s * 130 + (col ? 129 : 0);
        *(float4*)(smem + d * C1_A_BUF + ri * 32 + q * 16) =
            make_float4(0.f, 0.f, 0.f, 0.f);
    }

    const int rA = (lane & 7) + ((lane >> 3) & 1) * 8;
    const int qA = lane >> 4;
    int riA[4];
#pragma unroll
    for (int mt = 0; mt < 4; mt++) {
        int px = wpx + mt * 16 + rA;
        riA[mt] = (px >> 7) * 130 + (px & 127);
    }
    const int ocB = (lane & 7) + ((lane >> 4) << 3);
    const int qB = (lane >> 3) & 1;
    const int ocRow = wn + ocB;
    const uint32_t bSwz =
        sb + C1_OFF_B + (uint32_t)ocRow * 32 + (uint32_t)((qB ^ (ocRow >> 2)) & 1) * 16;

    float C[4][4][4];
#pragma unroll
    for (int i = 0; i < 4; i++)
#pragma unroll
        for (int j = 0; j < 4; j++)
#pragma unroll
            for (int k = 0; k < 4; k++) C[i][j][k] = 0.f;

    const char* ctrlBase = (const char*)g_ctrlp;
    const char* wBase = (const char*)g_w1p;

    auto stage = [&](int c, int d) {
        const char* srcA = ctrlBase + (size_t)(b * 8 + c) * (128 * 128 * 32);
        uint32_t aB = sb + d * C1_A_BUF;
#pragma unroll
        for (int it = 0; it < 4; it++) {
            int e = tid + it * 256;
            int s = e >> 8, r5 = e & 255;
            int x = r5 >> 1, q = r5 & 1;
            int gy = y0 - 1 + s;
            int gyc = gy < 0 ? 0 : (gy > 127 ? 127 : gy);
            const char* src = srcA + ((size_t)gyc * 128 + x) * 32 + q * 16;
            int ri = s * 130 + x + 1;
            uint32_t dst = aB + ri * 32 + ((q ^ (ri >> 2)) & 1) * 16;
            CPA16(dst, src, ((unsigned)gy < 128u) ? 16 : 0);
        }
        uint32_t bBf = sb + C1_OFF_B + d * C1_B_BUF;
        const char* srcB = wBase + (size_t)c * C1_B_BUF;
        for (int e = tid; e < 1152; e += 256)
            CPA16(bBf + e * 16, srcB + e * 16, 16);
        CP_COMMIT();
    };

    stage(0, 0);
    for (int c = 0; c < 8; c++) {
        if (c < 7) { stage(c + 1, (c + 1) & 1); CP_WAIT1(); }
        else CP_WAIT0();
        __syncthreads();

        const uint32_t aBuf = sb + (c & 1) * C1_A_BUF;
        const uint32_t bBuf = bSwz + (c & 1) * C1_B_BUF;
#pragma unroll
        for (int dy = 0; dy < 3; dy++) {
#pragma unroll
            for (int dx = 0; dx < 3; dx++) {
                const int tap = dy * 3 + dx;
                uint32_t bh[8];
                uint32_t bt = bBuf + tap * 2048;
                LDSM4(bh, bt);
                LDSM4(bh + 4, bt + 512);
                uint32_t a[16];
#pragma unroll
                for (int mt = 0; mt < 4; mt++) {
                    int rt = riA[mt] + dy * 130 + dx;
                    uint32_t ad = aBuf + rt * 32 + ((qA ^ (rt >> 2)) & 1) * 16;
                    LDSM4(a + mt * 4, ad);
                }
#pragma unroll
                for (int mt = 0; mt < 4; mt++)
#pragma unroll
                    for (int nt = 0; nt < 4; nt++)
                        MMA16816(C[mt][nt], a + mt * 4, bh[nt * 2], bh[nt * 2 + 1]);
            }
        }
        __syncthreads();
    }

    // epilogue: C -> smemT[oc][256 px] stride 265, bias/ReLU/BN -> fp16 g_hp
    {
        const int g2 = lane >> 2, t4 = lane & 3;
#pragma unroll
        for (int mt = 0; mt < 4; mt++) {
#pragma unroll
            for (int nt = 0; nt < 4; nt++) {
                int px = wpx + mt * 16 + g2;
                int oc = wn + nt * 8 + t4 * 2;
                smemT[oc * 265 + px] = C[mt][nt][0];
                smemT[(oc + 1) * 265 + px] = C[mt][nt][1];
                smemT[oc * 265 + px + 8] = C[mt][nt][2];
                smemT[(oc + 1) * 265 + px + 8] = C[mt][nt][3];
            }
        }
    }
    __syncthreads();
    for (int e = tid; e < 1024; e += 256) {
        int c = e >> 8, px = e & 255;
        int gy = y0 + (px >> 7), x = px & 127;
        uint32_t uh[8];
#pragma unroll
        for (int jp = 0; jp < 8; jp++) {
            __half oh[2];
#pragma unroll
            for (int t = 0; t < 2; t++) {
                int oc = c * 16 + 2 * jp + t;
                float val = 0.f;
                if (oc < C1) {
                    float acc = smemT[oc * 265 + px];
                    val = fmaxf(acc + smP[oc], 0.f) * smP[64 + oc] + smP[128 + oc];
                }
                oh[t] = __float2half(val);
            }
            uh[jp] = pack_h2(oh[0], oh[1]);
        }
        float4* dst = ((float4*)g_hp) + (((size_t)(b * 4 + c) * 128 + gy) * 128 + x) * 2;
        dst[0] = make_float4(__uint_as_float(uh[0]), __uint_as_float(uh[1]),
                             __uint_as_float(uh[2]), __uint_as_float(uh[3]));
        dst[1] = make_float4(__uint_as_float(uh[4]), __uint_as_float(uh[5]),
                             __uint_as_float(uh[6]), __uint_as_float(uh[7]));
    }
}

// ---------------------------------------------------------------------------
// conv2 mma: M=256 px, N=32 (18 used), K=4 chunks x 9 taps x 16.
// smem: A 2 x 16,640 = 33,280; B 2 x 9,216 @33,280; total 51,712
// ---------------------------------------------------------------------------
#define C2_OFF_B 33280
#define C2_B_BUF 9216
#define C2_SMEM 51712

__global__ void __launch_bounds__(256, 2) conv2_mma_kernel(const float* __restrict__ b2)
{
    extern __shared__ char smem[];
    float* smemT = (float*)smem;
    const uint32_t sb = smem_u32(smem);
    const int tid = threadIdx.x;
    const int lane = tid & 31;
    const int warp = tid >> 5;
    const int b = blockIdx.x >> 6;
    const int y0 = (blockIdx.x & 63) * 2;
    const int wpx = warp * 32;

    if (tid < 32) {
        int q = tid & 1, col = (tid >> 1) & 1, s = (tid >> 2) & 3, d = (tid >> 4) & 1;
        int ri = s * 130 + (col ? 129 : 0);
        *(float4*)(smem + d * C1_A_BUF + ri * 32 + q * 16) =
            make_float4(0.f, 0.f, 0.f, 0.f);
    }

    const int rA = (lane & 7) + ((lane >> 3) & 1) * 8;
    const int qA = lane >> 4;
    int riA[2];
#pragma unroll
    for (int mt = 0; mt < 2; mt++) {
        int px = wpx + mt * 16 + rA;
        riA[mt] = (px >> 7) * 130 + (px & 127);
    }
    const int ocB = (lane & 7) + ((lane >> 4) << 3);
    const int qB = (lane >> 3) & 1;
    const uint32_t bSwz =
        sb + C2_OFF_B + (uint32_t)ocB * 32 + (uint32_t)((qB ^ (ocB >> 2)) & 1) * 16;

    float C[2][4][4];
#pragma unroll
    for (int i = 0; i < 2; i++)
#pragma unroll
        for (int j = 0; j < 4; j++)
#pragma unroll
            for (int k = 0; k < 4; k++) C[i][j][k] = 0.f;

    const char* hpBase = (const char*)g_hp;
    const char* wBase = (const char*)g_w2p;

    auto stage = [&](int c, int d) {
        const char* srcA = hpBase + (size_t)(b * 4 + c) * (128 * 128 * 32);
        uint32_t aB = sb + d * C1_A_BUF;
#pragma unroll
        for (int it = 0; it < 4; it++) {
            int e = tid + it * 256;
            int s = e >> 8, r5 = e & 255;
            int x = r5 >> 1, q = r5 & 1;
            int gy = y0 - 1 + s;
            int gyc = gy < 0 ? 0 : (gy > 127 ? 127 : gy);
            const char* src = srcA + ((size_t)gyc * 128 + x) * 32 + q * 16;
            int ri = s * 130 + x + 1;
            uint32_t dst = aB + ri * 32 + ((q ^ (ri >> 2)) & 1) * 16;
            CPA16(dst, src, ((unsigned)gy < 128u) ? 16 : 0);
        }
        uint32_t bBf = sb + C2_OFF_B + d * C2_B_BUF;
        const char* srcB = wBase + (size_t)c * C2_B_BUF;
        for (int e = tid; e < 576; e += 256)
            CPA16(bBf + e * 16, srcB + e * 16, 16);
        CP_COMMIT();
    };

    stage(0, 0);
    for (int c = 0; c < 4; c++) {
        if (c < 3) { stage(c + 1, (c + 1) & 1); CP_WAIT1(); }
        else CP_WAIT0();
        __syncthreads();

        const uint32_t aBuf = sb + (c & 1) * C1_A_BUF;
        const uint32_t bBuf = bSwz + (c & 1) * C2_B_BUF;
#pragma unroll
        for (int dy = 0; dy < 3; dy++) {
#pragma unroll
            for (int dx = 0; dx < 3; dx++) {
                const int tap = dy * 3 + dx;
                uint32_t bh[8];
                uint32_t bt = bBuf + tap * 1024;
                LDSM4(bh, bt);
                LDSM4(bh + 4, bt + 512);
                uint32_t a[8];
#pragma unroll
                for (int mt = 0; mt < 2; mt++) {
                    int rt = riA[mt] + dy * 130 + dx;
                    uint32_t ad = aBuf + rt * 32 + ((qA ^ (rt >> 2)) & 1) * 16;
                    LDSM4(a + mt * 4, ad);
                }
#pragma unroll
                for (int mt = 0; mt < 2; mt++)
#pragma unroll
                    for (int nt = 0; nt < 4; nt++)
                        MMA16816(C[mt][nt], a + mt * 4, bh[nt * 2], bh[nt * 2 + 1]);
            }
        }
        __syncthreads();
    }

    {
        const int g2 = lane >> 2, t4 = lane & 3;
#pragma unroll
        for (int mt = 0; mt < 2; mt++) {
#pragma unroll
            for (int nt = 0; nt < 4; nt++) {
                int px = wpx + mt * 16 + g2;
                int oc = nt * 8 + t4 * 2;
                smemT[oc * 260 + px] = C[mt][nt][0];
                smemT[(oc + 1) * 260 + px] = C[mt][nt][1];
                smemT[oc * 260 + px + 8] = C[mt][nt][2];
                smemT[(oc + 1) * 260 + px + 8] = C[mt][nt][3];
            }
        }
    }
    __syncthreads();
    for (int e = tid; e < C2 * 64; e += 256) {
        int oc = e >> 6, pq = e & 63;
        int px0 = pq * 4;
        int gy = y0 + (px0 >> 7), x = px0 & 127;
        float bv = b2[oc];
        float4 v = *(float4*)(smemT + oc * 260 + px0);
        v.x += bv; v.y += bv; v.z += bv; v.w += bv;
        *(float4*)(g_cond + (((size_t)b * C2 + oc) * NH + gy) * NW + x) = v;
    }
}

// ---------------------------------------------------------------------------
// translate: 4 cells/thread in x, register reuse of image float4 loads.
// block (32, 8): tx = x-group (4 float4-cols), ty = cellY within block.
// ---------------------------------------------------------------------------
__global__ __launch_bounds__(256) void translate_kernel(
    const float* __restrict__ image, float* __restrict__ out)
{
    const int tx = threadIdx.x;               // 0..31
    const int cellY = blockIdx.x * 8 + threadIdx.y;
    const int ch = blockIdx.y;
    const int b = blockIdx.z;
    const int g = ch / 3;
    const int x0 = tx * 4;                    // float4 col base

    float wk[4][9];
    const float* cond_b = g_cond + ((size_t)b * C2 + g * 9) * NH * NW;
#pragma unroll
    for (int k = 0; k < 9; k++) {
        const float* row = cond_b + (size_t)k * NH * NW + (size_t)cellY * NW;
#pragma unroll
        for (int c = 0; c < 4; c++) wk[c][k] = row[x0 + c];
    }

    const float4* img4 = (const float4*)image + (size_t)(b * 6 + ch) * HH * (WW / 4);
    float4* out4 = (float4*)out + (size_t)(b * 6 + ch) * HH * (WW / 4);

#pragma unroll
    for (int r = 0; r < 4; r++) {
        int y = cellY * 4 + r;
        float4 acc[4];
#pragma unroll
        for (int c = 0; c < 4; c++) acc[c] = make_float4(0.f, 0.f, 0.f, 0.f);
#pragma unroll
        for (int j = 0; j < 3; j++) {
            int yy = y + j * 4 - 4;
            if ((unsigned)yy >= (unsigned)HH) continue;
            const float4* rowp = img4 + (size_t)yy * (WW / 4);
            float4 v[6];
#pragma unroll
            for (int t = 0; t < 6; t++) {
                int xf = x0 - 1 + t;
                v[t] = ((unsigned)xf < (unsigned)(WW / 4))
                           ? rowp[xf] : make_float4(0.f, 0.f, 0.f, 0.f);
            }
#pragma unroll
            for (int c = 0; c < 4; c++) {
#pragma unroll
                for (int i = 0; i < 3; i++) {
                    float w = wk[c][i * 3 + j];
                    float4 vv = v[c + i];
                    acc[c].x += vv.x * w; acc[c].y += vv.y * w;
                    acc[c].z += vv.z * w; acc[c].w += vv.w * w;
                }
            }
        }
#pragma unroll
        for (int c = 0; c < 4; c++)
            out4[(size_t)y * (WW / 4) + x0 + c] = acc[c];
    }
}

// ---------------------------------------------------------------------------
extern "C" void kernel_launch(void* const* d_in, const int* in_sizes, int n_in,
                              void* d_out, int out_size)
{
    const float* image = (const float*)d_in[0];
    const float* ctrl  = (const float*)d_in[1];
    const float* w1    = (const float*)d_in[2];
    const float* b1    = (const float*)d_in[3];
    const float* gamma = (const float*)d_in[4];
    const float* beta  = (const float*)d_in[5];
    const float* mean  = (const float*)d_in[6];
    const float* var   = (const float*)d_in[7];
    const float* w2    = (const float*)d_in[8];
    const float* b2    = (const float*)d_in[9];
    float* out = (float*)d_out;

    static int smem_set = 0;
    if (!smem_set) {
        cudaFuncSetAttribute(conv1_mma_kernel,
                             cudaFuncAttributeMaxDynamicSharedMemorySize, C1_SMEM);
        cudaFuncSetAttribute(conv2_mma_kernel,
                             cudaFuncAttributeMaxDynamicSharedMemorySize, C2_SMEM);
        smem_set = 1;
    }

    prep_ctrl_kernel<<<BB * 8 * NH, 256>>>(ctrl);
    prep_w1_kernel<<<288, 256>>>(w1);
    prep_w2_kernel<<<72, 256>>>(w2);
    conv1_mma_kernel<<<BB * 64, 256, C1_SMEM>>>(b1, gamma, beta, mean, var);
    conv2_mma_kernel<<<BB * 64, 256, C2_SMEM>>>(b2);
    translate_kernel<<<dim3(16, 6, BB), dim3(32, 8)>>>(image, out);
}

// round 9
// speedup vs baseline: 4.8311x; 1.0423x over previous
#include <cuda_runtime.h>
#include <cuda_fp16.h>
#include <cstdint>

#define BB 8
#define CC 128
#define NH 128
#define NW 128
#define C1 50
#define C2 18
#define HH 512
#define WW 512

// ---------------------------------------------------------------------------
// Device-global scratch
// ---------------------------------------------------------------------------
__device__ __align__(16) __half g_ctrlp[(size_t)BB * 8 * NH * NW * 16];
__device__ __align__(16) __half g_hp[(size_t)BB * 4 * NH * NW * 16];
__device__ float g_cond[(size_t)BB * C2 * NH * NW];
__device__ __align__(16) __half g_w1p[8 * 9 * 64 * 16];
__device__ __align__(16) __half g_w2p[4 * 9 * 32 * 16];

__device__ __forceinline__ uint32_t smem_u32(const void* p) {
    uint32_t a;
    asm("{ .reg .u64 t; cvta.to.shared.u64 t, %1; cvt.u32.u64 %0, t; }"
        : "=r"(a) : "l"(p));
    return a;
}

#define LDSM4(r, a)                                                            \
    asm volatile("ldmatrix.sync.aligned.m8n8.x4.shared.b16 {%0,%1,%2,%3}, [%4];" \
        : "=r"((r)[0]), "=r"((r)[1]), "=r"((r)[2]), "=r"((r)[3]) : "r"(a))

#define MMA16816(c, a, b0, b1)                                                 \
    asm volatile("mma.sync.aligned.m16n8k16.row.col.f32.f16.f16.f32 "          \
        "{%0,%1,%2,%3},{%4,%5,%6,%7},{%8,%9},{%0,%1,%2,%3};"                   \
        : "+f"((c)[0]), "+f"((c)[1]), "+f"((c)[2]), "+f"((c)[3])               \
        : "r"((a)[0]), "r"((a)[1]), "r"((a)[2]), "r"((a)[3]), "r"(b0), "r"(b1))

#define CPA16(dst, src, sz)                                                    \
    asm volatile("cp.async.cg.shared.global [%0], [%1], 16, %2;"               \
        :: "r"(dst), "l"(src), "r"(sz) : "memory")
#define CP_COMMIT() asm volatile("cp.async.commit_group;" ::: "memory")
#define CP_WAIT1()  asm volatile("cp.async.wait_group 1;" ::: "memory")
#define CP_WAIT0()  asm volatile("cp.async.wait_group 0;" ::: "memory")

__device__ __forceinline__ uint32_t pack_h2(__half a, __half b) {
    return (uint32_t)__half_as_ushort(a) | ((uint32_t)__half_as_ushort(b) << 16);
}

// ---------------------------------------------------------------------------
// prep_all: [0, 8192) ctrl conversion; [8192, 8552) weight packing
// ---------------------------------------------------------------------------
__global__ __launch_bounds__(256) void prep_all_kernel(
    const float* __restrict__ ctrl, const float* __restrict__ w1,
    const float* __restrict__ w2)
{
    __shared__ float sm[16 * 132];
    const int bid = blockIdx.x;
    const int tid = threadIdx.x;

    if (bid < 8192) {
        // ctrl: fp32 -> fp16 [b][chunk][y][x][q2]
        const int y = bid & 127;
        const int bc = bid >> 7;
        const int chunk = bc & 7;
        const int b = bc >> 3;

        const float* src = ctrl + (((size_t)b * CC + chunk * 16) * NH + y) * NW;
        for (int e = tid; e < 2048; e += 256) {
            int c = e >> 7, x = e & 127;
            sm[c * 132 + x] = src[(size_t)c * NH * NW + x];
        }
        __syncthreads();

        const int px = tid & 127, q = tid >> 7;
        uint32_t u[4];
#pragma unroll
        for (int jp = 0; jp < 4; jp++) {
            __half o[2];
#pragma unroll
            for (int t = 0; t < 2; t++)
                o[t] = __float2half(sm[(q * 8 + 2 * jp + t) * 132 + px]);
            u[jp] = pack_h2(o[0], o[1]);
        }
        float4* dst = ((float4*)g_ctrlp) + (((size_t)bid * 128 + px) * 2 + q);
        dst[0] = make_float4(__uint_as_float(u[0]), __uint_as_float(u[1]),
                             __uint_as_float(u[2]), __uint_as_float(u[3]));
    } else {
        int idx = (bid - 8192) * 256 + tid;
        if (idx < 8 * 9 * 64 * 16) {
            int jc = idx & 15;
            int oc = (idx >> 4) & 63;
            int r = idx >> 10;
            int tap = r % 9, chunk = r / 9;
            int dy = tap / 3, dx = tap % 3;
            float w = 0.f;
            if (oc < C1)
                w = w1[((oc * CC + chunk * 16 + jc) * 3 + dy) * 3 + dx];
            int q = (jc >> 3) ^ ((oc >> 2) & 1);
            g_w1p[((chunk * 9 + tap) * 64 + oc) * 16 + q * 8 + (jc & 7)] =
                __float2half(w);
        } else {
            int i2 = idx - 8 * 9 * 64 * 16;
            if (i2 < 4 * 9 * 32 * 16) {
                int jc = i2 & 15;
                int oc = (i2 >> 4) & 31;
                int r = i2 >> 9;
                int tap = r % 9, chunk = r / 9;
                int dy = tap / 3, dx = tap % 3;
                int cin = chunk * 16 + jc;
                float w = 0.f;
                if (oc < C2 && cin < C1)
                    w = w2[((oc * C1 + cin) * 3 + dy) * 3 + dx];
                int q = (jc >> 3) ^ ((oc >> 2) & 1);
                g_w2p[((chunk * 9 + tap) * 32 + oc) * 16 + q * 8 + (jc & 7)] =
                    __float2half(w);
            }
        }
    }
}

// ---------------------------------------------------------------------------
// conv1 mma (unchanged from R8): M=256, N=64, K=8x9x16, double-buffered
// ---------------------------------------------------------------------------
#define C1_A_BUF 16640
#define C1_OFF_B 33280
#define C1_B_BUF 18432
#define C1_OFF_P 70144
#define C1_SMEM 70912

__global__ void __launch_bounds__(256, 2) conv1_mma_kernel(
    const float* __restrict__ b1, const float* __restrict__ gamma,
    const float* __restrict__ beta, const float* __restrict__ mean,
    const float* __restrict__ var)
{
    extern __shared__ char smem[];
    float* smemT = (float*)smem;
    float* smP = (float*)(smem + C1_OFF_P);
    const uint32_t sb = smem_u32(smem);
    const int tid = threadIdx.x;
    const int lane = tid & 31;
    const int warp = tid >> 5;
    const int b = blockIdx.x >> 6;
    const int y0 = (blockIdx.x & 63) * 2;
    const int wpx = (warp >> 1) * 64;
    const int wn = (warp & 1) * 32;

    if (tid < 64) {
        float s = 0.f, bb = 0.f, b1v = 0.f;
        if (tid < C1) {
            s = gamma[tid] * rsqrtf(var[tid] + 1e-5f);
            bb = beta[tid] - mean[tid] * s;
            b1v = b1[tid];
        }
        smP[tid] = b1v; smP[64 + tid] = s; smP[128 + tid] = bb;
    }
    if (tid < 32) {
        int q = tid & 1, col = (tid >> 1) & 1, s = (tid >> 2) & 3, d = (tid >> 4) & 1;
        int ri = s * 130 + (col ? 129 : 0);
        *(float4*)(smem + d * C1_A_BUF + ri * 32 + q * 16) =
            make_float4(0.f, 0.f, 0.f, 0.f);
    }

    const int rA = (lane & 7) + ((lane >> 3) & 1) * 8;
    const int qA = lane >> 4;
    int riA[4];
#pragma unroll
    for (int mt = 0; mt < 4; mt++) {
        int px = wpx + mt * 16 + rA;
        riA[mt] = (px >> 7) * 130 + (px & 127);
    }
    const int ocB = (lane & 7) + ((lane >> 4) << 3);
    const int qB = (lane >> 3) & 1;
    const int ocRow = wn + ocB;
    const uint32_t bSwz =
        sb + C1_OFF_B + (uint32_t)ocRow * 32 + (uint32_t)((qB ^ (ocRow >> 2)) & 1) * 16;

    float C[4][4][4];
#pragma unroll
    for (int i = 0; i < 4; i++)
#pragma unroll
        for (int j = 0; j < 4; j++)
#pragma unroll
            for (int k = 0; k < 4; k++) C[i][j][k] = 0.f;

    const char* ctrlBase = (const char*)g_ctrlp;
    const char* wBase = (const char*)g_w1p;

    auto stage = [&](int c, int d) {
        const char* srcA = ctrlBase + (size_t)(b * 8 + c) * (128 * 128 * 32);
        uint32_t aB = sb + d * C1_A_BUF;
#pragma unroll
        for (int it = 0; it < 4; it++) {
            int e = tid + it * 256;
            int s = e >> 8, r5 = e & 255;
            int x = r5 >> 1, q = r5 & 1;
            int gy = y0 - 1 + s;
            int gyc = gy < 0 ? 0 : (gy > 127 ? 127 : gy);
            const char* src = srcA + ((size_t)gyc * 128 + x) * 32 + q * 16;
            int ri = s * 130 + x + 1;
            uint32_t dst = aB + ri * 32 + ((q ^ (ri >> 2)) & 1) * 16;
            CPA16(dst, src, ((unsigned)gy < 128u) ? 16 : 0);
        }
        uint32_t bBf = sb + C1_OFF_B + d * C1_B_BUF;
        const char* srcB = wBase + (size_t)c * C1_B_BUF;
        for (int e = tid; e < 1152; e += 256)
            CPA16(bBf + e * 16, srcB + e * 16, 16);
        CP_COMMIT();
    };

    stage(0, 0);
    for (int c = 0; c < 8; c++) {
        if (c < 7) { stage(c + 1, (c + 1) & 1); CP_WAIT1(); }
        else CP_WAIT0();
        __syncthreads();

        const uint32_t aBuf = sb + (c & 1) * C1_A_BUF;
        const uint32_t bBuf = bSwz + (c & 1) * C1_B_BUF;
#pragma unroll
        for (int dy = 0; dy < 3; dy++) {
#pragma unroll
            for (int dx = 0; dx < 3; dx++) {
                const int tap = dy * 3 + dx;
                uint32_t bh[8];
                uint32_t bt = bBuf + tap * 2048;
                LDSM4(bh, bt);
                LDSM4(bh + 4, bt + 512);
                uint32_t a[16];
#pragma unroll
                for (int mt = 0; mt < 4; mt++) {
                    int rt = riA[mt] + dy * 130 + dx;
                    uint32_t ad = aBuf + rt * 32 + ((qA ^ (rt >> 2)) & 1) * 16;
                    LDSM4(a + mt * 4, ad);
                }
#pragma unroll
                for (int mt = 0; mt < 4; mt++)
#pragma unroll
                    for (int nt = 0; nt < 4; nt++)
                        MMA16816(C[mt][nt], a + mt * 4, bh[nt * 2], bh[nt * 2 + 1]);
            }
        }
        __syncthreads();
    }

    {
        const int g2 = lane >> 2, t4 = lane & 3;
#pragma unroll
        for (int mt = 0; mt < 4; mt++) {
#pragma unroll
            for (int nt = 0; nt < 4; nt++) {
                int px = wpx + mt * 16 + g2;
                int oc = wn + nt * 8 + t4 * 2;
                smemT[oc * 265 + px] = C[mt][nt][0];
                smemT[(oc + 1) * 265 + px] = C[mt][nt][1];
                smemT[oc * 265 + px + 8] = C[mt][nt][2];
                smemT[(oc + 1) * 265 + px + 8] = C[mt][nt][3];
            }
        }
    }
    __syncthreads();
    for (int e = tid; e < 1024; e += 256) {
        int c = e >> 8, px = e & 255;
        int gy = y0 + (px >> 7), x = px & 127;
        uint32_t uh[8];
#pragma unroll
        for (int jp = 0; jp < 8; jp++) {
            __half oh[2];
#pragma unroll
            for (int t = 0; t < 2; t++) {
                int oc = c * 16 + 2 * jp + t;
                float val = 0.f;
                if (oc < C1) {
                    float acc = smemT[oc * 265 + px];
                    val = fmaxf(acc + smP[oc], 0.f) * smP[64 + oc] + smP[128 + oc];
                }
                oh[t] = __float2half(val);
            }
            uh[jp] = pack_h2(oh[0], oh[1]);
        }
        float4* dst = ((float4*)g_hp) + (((size_t)(b * 4 + c) * 128 + gy) * 128 + x) * 2;
        dst[0] = make_float4(__uint_as_float(uh[0]), __uint_as_float(uh[1]),
                             __uint_as_float(uh[2]), __uint_as_float(uh[3]));
        dst[1] = make_float4(__uint_as_float(uh[4]), __uint_as_float(uh[5]),
                             __uint_as_float(uh[6]), __uint_as_float(uh[7]));
    }
}

// ---------------------------------------------------------------------------
// conv2 mma: M=512 (4 rows/CTA), N=32 (18 used), K=4x9x16. grid=256 (1 wave).
// smem: A 2 x 24,960 = 49,920; B 2 x 9,216 @49,920; total 68,352
// ---------------------------------------------------------------------------
#define C2_A_BUF 24960
#define C2_OFF_B 49920
#define C2_B_BUF 9216
#define C2_SMEM 68352

__global__ void __launch_bounds__(256, 2) conv2_mma_kernel(const float* __restrict__ b2)
{
    extern __shared__ char smem[];
    float* smemT = (float*)smem;           // 32 x 516 floats = 66,048B (after mainloop)
    const uint32_t sb = smem_u32(smem);
    const int tid = threadIdx.x;
    const int lane = tid & 31;
    const int warp = tid >> 5;
    const int b = blockIdx.x >> 5;
    const int y0 = (blockIdx.x & 31) * 4;
    const int wpx = warp * 64;             // 8 warps x 64 px = 512

    // zero halo columns: ri = s*130 + {0,129}, s in 0..5, both buffers, both q
    if (tid < 48) {
        int q = tid & 1, col = (tid >> 1) & 1, s = (tid >> 2) % 6, d = tid >= 24 ? 1 : 0;
        int ri = s * 130 + (col ? 129 : 0);
        *(float4*)(smem + d * C2_A_BUF + ri * 32 + q * 16) =
            make_float4(0.f, 0.f, 0.f, 0.f);
    }

    const int rA = (lane & 7) + ((lane >> 3) & 1) * 8;
    const int qA = lane >> 4;
    int riA[4];
#pragma unroll
    for (int mt = 0; mt < 4; mt++) {
        int px = wpx + mt * 16 + rA;
        riA[mt] = (px >> 7) * 130 + (px & 127);
    }
    const int ocB = (lane & 7) + ((lane >> 4) << 3);
    const int qB = (lane >> 3) & 1;
    const uint32_t bSwz =
        sb + C2_OFF_B + (uint32_t)ocB * 32 + (uint32_t)((qB ^ (ocB >> 2)) & 1) * 16;

    float C[4][4][4];
#pragma unroll
    for (int i = 0; i < 4; i++)
#pragma unroll
        for (int j = 0; j < 4; j++)
#pragma unroll
            for (int k = 0; k < 4; k++) C[i][j][k] = 0.f;

    const char* hpBase = (const char*)g_hp;
    const char* wBase = (const char*)g_w2p;

    auto stage = [&](int c, int d) {
        const char* srcA = hpBase + (size_t)(b * 4 + c) * (128 * 128 * 32);
        uint32_t aB = sb + d * C2_A_BUF;
#pragma unroll
        for (int it = 0; it < 6; it++) {
            int e = tid + it * 256;
            int s = e >> 8, r5 = e & 255;
            int x = r5 >> 1, q = r5 & 1;
            int gy = y0 - 1 + s;
            int gyc = gy < 0 ? 0 : (gy > 127 ? 127 : gy);
            const char* src = srcA + ((size_t)gyc * 128 + x) * 32 + q * 16;
            int ri = s * 130 + x + 1;
            uint32_t dst = aB + ri * 32 + ((q ^ (ri >> 2)) & 1) * 16;
            CPA16(dst, src, ((unsigned)gy < 128u) ? 16 : 0);
        }
        uint32_t bBf = sb + C2_OFF_B + d * C2_B_BUF;
        const char* srcB = wBase + (size_t)c * C2_B_BUF;
        for (int e = tid; e < 576; e += 256)
            CPA16(bBf + e * 16, srcB + e * 16, 16);
        CP_COMMIT();
    };

    stage(0, 0);
    for (int c = 0; c < 4; c++) {
        if (c < 3) { stage(c + 1, (c + 1) & 1); CP_WAIT1(); }
        else CP_WAIT0();
        __syncthreads();

        const uint32_t aBuf = sb + (c & 1) * C2_A_BUF;
        const uint32_t bBuf = bSwz + (c & 1) * C2_B_BUF;
#pragma unroll
        for (int dy = 0; dy < 3; dy++) {
#pragma unroll
            for (int dx = 0; dx < 3; dx++) {
                const int tap = dy * 3 + dx;
                uint32_t bh[8];
                uint32_t bt = bBuf + tap * 1024;
                LDSM4(bh, bt);
                LDSM4(bh + 4, bt + 512);
                uint32_t a[16];
#pragma unroll
                for (int mt = 0; mt < 4; mt++) {
                    int rt = riA[mt] + dy * 130 + dx;
                    uint32_t ad = aBuf + rt * 32 + ((qA ^ (rt >> 2)) & 1) * 16;
                    LDSM4(a + mt * 4, ad);
                }
#pragma unroll
                for (int mt = 0; mt < 4; mt++)
#pragma unroll
                    for (int nt = 0; nt < 4; nt++)
                        MMA16816(C[mt][nt], a + mt * 4, bh[nt * 2], bh[nt * 2 + 1]);
            }
        }
        __syncthreads();
    }

    // epilogue: smemT[oc][512] stride 516, +b2, fp32 stores
    {
        const int g2 = lane >> 2, t4 = lane & 3;
#pragma unroll
        for (int mt = 0; mt < 4; mt++) {
#pragma unroll
            for (int nt = 0; nt < 4; nt++) {
                int px = wpx + mt * 16 + g2;
                int oc = nt * 8 + t4 * 2;
                smemT[oc * 516 + px] = C[mt][nt][0];
                smemT[(oc + 1) * 516 + px] = C[mt][nt][1];
                smemT[oc * 516 + px + 8] = C[mt][nt][2];
                smemT[(oc + 1) * 516 + px + 8] = C[mt][nt][3];
            }
        }
    }
    __syncthreads();
    for (int e = tid; e < C2 * 128; e += 256) {
        int oc = e >> 7, pq = e & 127;
        int px0 = pq * 4;
        int gy = y0 + (px0 >> 7), x = px0 & 127;
        float bv = b2[oc];
        float4 v = *(float4*)(smemT + oc * 516 + px0);
        v.x += bv; v.y += bv; v.z += bv; v.w += bv;
        *(float4*)(g_cond + (((size_t)b * C2 + oc) * NH + gy) * NW + x) = v;
    }
}

// ---------------------------------------------------------------------------
// translate (unchanged from R8)
// ---------------------------------------------------------------------------
__global__ __launch_bounds__(256) void translate_kernel(
    const float* __restrict__ image, float* __restrict__ out)
{
    const int tx = threadIdx.x;
    const int cellY = blockIdx.x * 8 + threadIdx.y;
    const int ch = blockIdx.y;
    const int b = blockIdx.z;
    const int g = ch / 3;
    const int x0 = tx * 4;

    float wk[4][9];
    const float* cond_b = g_cond + ((size_t)b * C2 + g * 9) * NH * NW;
#pragma unroll
    for (int k = 0; k < 9; k++) {
        const float* row = cond_b + (size_t)k * NH * NW + (size_t)cellY * NW;
#pragma unroll
        for (int c = 0; c < 4; c++) wk[c][k] = row[x0 + c];
    }

    const float4* img4 = (const float4*)image + (size_t)(b * 6 + ch) * HH * (WW / 4);
    float4* out4 = (float4*)out + (size_t)(b * 6 + ch) * HH * (WW / 4);

#pragma unroll
    for (int r = 0; r < 4; r++) {
        int y = cellY * 4 + r;
        float4 acc[4];
#pragma unroll
        for (int c = 0; c < 4; c++) acc[c] = make_float4(0.f, 0.f, 0.f, 0.f);
#pragma unroll
        for (int j = 0; j < 3; j++) {
            int yy = y + j * 4 - 4;
            if ((unsigned)yy >= (unsigned)HH) continue;
            const float4* rowp = img4 + (size_t)yy * (WW / 4);
            float4 v[6];
#pragma unroll
            for (int t = 0; t < 6; t++) {
                int xf = x0 - 1 + t;
                v[t] = ((unsigned)xf < (unsigned)(WW / 4))
                           ? rowp[xf] : make_float4(0.f, 0.f, 0.f, 0.f);
            }
#pragma unroll
            for (int c = 0; c < 4; c++) {
#pragma unroll
                for (int i = 0; i < 3; i++) {
                    float w = wk[c][i * 3 + j];
                    float4 vv = v[c + i];
                    acc[c].x += vv.x * w; acc[c].y += vv.y * w;
                    acc[c].z += vv.z * w; acc[c].w += vv.w * w;
                }
            }
        }
#pragma unroll
        for (int c = 0; c < 4; c++)
            out4[(size_t)y * (WW / 4) + x0 + c] = acc[c];
    }
}

// ---------------------------------------------------------------------------
extern "C" void kernel_launch(void* const* d_in, const int* in_sizes, int n_in,
                              void* d_out, int out_size)
{
    const float* image = (const float*)d_in[0];
    const float* ctrl  = (const float*)d_in[1];
    const float* w1    = (const float*)d_in[2];
    const float* b1    = (const float*)d_in[3];
    const float* gamma = (const float*)d_in[4];
    const float* beta  = (const float*)d_in[5];
    const float* mean  = (const float*)d_in[6];
    const float* var   = (const float*)d_in[7];
    const float* w2    = (const float*)d_in[8];
    const float* b2    = (const float*)d_in[9];
    float* out = (float*)d_out;

    static int smem_set = 0;
    if (!smem_set) {
        cudaFuncSetAttribute(conv1_mma_kernel,
                             cudaFuncAttributeMaxDynamicSharedMemorySize, C1_SMEM);
        cudaFuncSetAttribute(conv2_mma_kernel,
                             cudaFuncAttributeMaxDynamicSharedMemorySize, C2_SMEM);
        smem_set = 1;
    }

    prep_all_kernel<<<8192 + 360, 256>>>(ctrl, w1, w2);
    conv1_mma_kernel<<<BB * 64, 256, C1_SMEM>>>(b1, gamma, beta, mean, var);
    conv2_mma_kernel<<<BB * 32, 256, C2_SMEM>>>(b2);
    translate_kernel<<<dim3(16, 6, BB), dim3(32, 8)>>>(image, out);
}

// round 10
// speedup vs baseline: 6.1060x; 1.2639x over previous
#include <cuda_runtime.h>
#include <cuda_fp16.h>
#include <cstdint>

#define BB 8
#define CC 128
#define NH 128
#define NW 128
#define C1 50
#define C2 18
#define HH 512
#define WW 512

// ---------------------------------------------------------------------------
// Device-global scratch
// ---------------------------------------------------------------------------
__device__ __align__(16) __half g_ctrlp[(size_t)BB * 8 * NH * NW * 16];
__device__ __align__(16) __half g_hp[(size_t)BB * 4 * NH * NW * 16];
__device__ float g_cond[(size_t)BB * C2 * NH * NW];
__device__ __align__(16) __half g_w1p[8 * 9 * 64 * 16];
__device__ __align__(16) __half g_w2p[4 * 9 * 32 * 16];

__device__ __forceinline__ uint32_t smem_u32(const void* p) {
    uint32_t a;
    asm("{ .reg .u64 t; cvta.to.shared.u64 t, %1; cvt.u32.u64 %0, t; }"
        : "=r"(a) : "l"(p));
    return a;
}

#define LDSM4(r, a)                                                            \
    asm volatile("ldmatrix.sync.aligned.m8n8.x4.shared.b16 {%0,%1,%2,%3}, [%4];" \
        : "=r"((r)[0]), "=r"((r)[1]), "=r"((r)[2]), "=r"((r)[3]) : "r"(a))

#define MMA16816(c, a, b0, b1)                                                 \
    asm volatile("mma.sync.aligned.m16n8k16.row.col.f32.f16.f16.f32 "          \
        "{%0,%1,%2,%3},{%4,%5,%6,%7},{%8,%9},{%0,%1,%2,%3};"                   \
        : "+f"((c)[0]), "+f"((c)[1]), "+f"((c)[2]), "+f"((c)[3])               \
        : "r"((a)[0]), "r"((a)[1]), "r"((a)[2]), "r"((a)[3]), "r"(b0), "r"(b1))

#define CPA16(dst, src, sz)                                                    \
    asm volatile("cp.async.cg.shared.global [%0], [%1], 16, %2;"               \
        :: "r"(dst), "l"(src), "r"(sz) : "memory")
#define CP_COMMIT() asm volatile("cp.async.commit_group;" ::: "memory")
#define CP_WAIT1()  asm volatile("cp.async.wait_group 1;" ::: "memory")
#define CP_WAIT0()  asm volatile("cp.async.wait_group 0;" ::: "memory")

__device__ __forceinline__ uint32_t pack_h2(__half a, __half b) {
    return (uint32_t)__half_as_ushort(a) | ((uint32_t)__half_as_ushort(b) << 16);
}

// ---------------------------------------------------------------------------
// prep_all: [0, 2048) ctrl conversion (4 y-rows per block); then weight packing
// ---------------------------------------------------------------------------
__global__ __launch_bounds__(256) void prep_all_kernel(
    const float* __restrict__ ctrl, const float* __restrict__ w1,
    const float* __restrict__ w2)
{
    __shared__ float sm[16 * 4 * 132];
    const int bid = blockIdx.x;
    const int tid = threadIdx.x;

    if (bid < 2048) {
        // block = (b, chunk, ys): 16 cins x 4 rows x 128 px
        const int ys = bid & 31;
        const int bc = bid >> 5;
        const int chunk = bc & 7;
        const int b = bc >> 3;

        const float* src = ctrl + (((size_t)b * CC + chunk * 16) * NH + ys * 4) * NW;
        // read: 64 (c,yl) rows x 32 float4, fully coalesced
#pragma unroll
        for (int it = 0; it < 8; it++) {
            int e = tid + it * 256;
            int r = e >> 5, xi = e & 31;
            int c = r >> 2, yl = r & 3;
            float4 v = *(const float4*)(src + (size_t)c * NH * NW + yl * NW + xi * 4);
            *(float4*)(sm + (c * 4 + yl) * 132 + xi * 4) = v;
        }
        __syncthreads();

        // write: (yl,x,q) tasks; each packs 8 halves = 1 float4
#pragma unroll
        for (int it = 0; it < 4; it++) {
            int idx = tid + it * 256;
            int q = idx & 1, x = (idx >> 1) & 127, yl = idx >> 8;
            uint32_t u[4];
#pragma unroll
            for (int jp = 0; jp < 4; jp++) {
                int c0 = q * 8 + 2 * jp;
                __half o0 = __float2half(sm[(c0 * 4 + yl) * 132 + x]);
                __half o1 = __float2half(sm[((c0 + 1) * 4 + yl) * 132 + x]);
                u[jp] = pack_h2(o0, o1);
            }
            int y = ys * 4 + yl;
            float4* dst = ((float4*)g_ctrlp) +
                (((size_t)(bc * 128 + y) * 128 + x) * 2 + q);
            dst[0] = make_float4(__uint_as_float(u[0]), __uint_as_float(u[1]),
                                 __uint_as_float(u[2]), __uint_as_float(u[3]));
        }
    } else {
        int idx = (bid - 2048) * 256 + tid;
        if (idx < 8 * 9 * 64 * 16) {
            int jc = idx & 15;
            int oc = (idx >> 4) & 63;
            int r = idx >> 10;
            int tap = r % 9, chunk = r / 9;
            int dy = tap / 3, dx = tap % 3;
            float w = 0.f;
            if (oc < C1)
                w = w1[((oc * CC + chunk * 16 + jc) * 3 + dy) * 3 + dx];
            int q = (jc >> 3) ^ ((oc >> 2) & 1);
            g_w1p[((chunk * 9 + tap) * 64 + oc) * 16 + q * 8 + (jc & 7)] =
                __float2half(w);
        } else {
            int i2 = idx - 8 * 9 * 64 * 16;
            if (i2 < 4 * 9 * 32 * 16) {
                int jc = i2 & 15;
                int oc = (i2 >> 4) & 31;
                int r = i2 >> 9;
                int tap = r % 9, chunk = r / 9;
                int dy = tap / 3, dx = tap % 3;
                int cin = chunk * 16 + jc;
                float w = 0.f;
                if (oc < C2 && cin < C1)
                    w = w2[((oc * C1 + cin) * 3 + dy) * 3 + dx];
                int q = (jc >> 3) ^ ((oc >> 2) & 1);
                g_w2p[((chunk * 9 + tap) * 32 + oc) * 16 + q * 8 + (jc & 7)] =
                    __float2half(w);
            }
        }
    }
}

// ---------------------------------------------------------------------------
// conv1 mma (unchanged): M=256, N=64, K=8x9x16, double-buffered
// ---------------------------------------------------------------------------
#define C1_A_BUF 16640
#define C1_OFF_B 33280
#define C1_B_BUF 18432
#define C1_OFF_P 70144
#define C1_SMEM 70912

__global__ void __launch_bounds__(256, 2) conv1_mma_kernel(
    const float* __restrict__ b1, const float* __restrict__ gamma,
    const float* __restrict__ beta, const float* __restrict__ mean,
    const float* __restrict__ var)
{
    extern __shared__ char smem[];
    float* smemT = (float*)smem;
    float* smP = (float*)(smem + C1_OFF_P);
    const uint32_t sb = smem_u32(smem);
    const int tid = threadIdx.x;
    const int lane = tid & 31;
    const int warp = tid >> 5;
    const int b = blockIdx.x >> 6;
    const int y0 = (blockIdx.x & 63) * 2;
    const int wpx = (warp >> 1) * 64;
    const int wn = (warp & 1) * 32;

    if (tid < 64) {
        float s = 0.f, bb = 0.f, b1v = 0.f;
        if (tid < C1) {
            s = gamma[tid] * rsqrtf(var[tid] + 1e-5f);
            bb = beta[tid] - mean[tid] * s;
            b1v = b1[tid];
        }
        smP[tid] = b1v; smP[64 + tid] = s; smP[128 + tid] = bb;
    }
    if (tid < 32) {
        int q = tid & 1, col = (tid >> 1) & 1, s = (tid >> 2) & 3, d = (tid >> 4) & 1;
        int ri = s * 130 + (col ? 129 : 0);
        *(float4*)(smem + d * C1_A_BUF + ri * 32 + q * 16) =
            make_float4(0.f, 0.f, 0.f, 0.f);
    }

    const int rA = (lane & 7) + ((lane >> 3) & 1) * 8;
    const int qA = lane >> 4;
    int riA[4];
#pragma unroll
    for (int mt = 0; mt < 4; mt++) {
        int px = wpx + mt * 16 + rA;
        riA[mt] = (px >> 7) * 130 + (px & 127);
    }
    const int ocB = (lane & 7) + ((lane >> 4) << 3);
    const int qB = (lane >> 3) & 1;
    const int ocRow = wn + ocB;
    const uint32_t bSwz =
        sb + C1_OFF_B + (uint32_t)ocRow * 32 + (uint32_t)((qB ^ (ocRow >> 2)) & 1) * 16;

    float C[4][4][4];
#pragma unroll
    for (int i = 0; i < 4; i++)
#pragma unroll
        for (int j = 0; j < 4; j++)
#pragma unroll
            for (int k = 0; k < 4; k++) C[i][j][k] = 0.f;

    const char* ctrlBase = (const char*)g_ctrlp;
    const char* wBase = (const char*)g_w1p;

    auto stage = [&](int c, int d) {
        const char* srcA = ctrlBase + (size_t)(b * 8 + c) * (128 * 128 * 32);
        uint32_t aB = sb + d * C1_A_BUF;
#pragma unroll
        for (int it = 0; it < 4; it++) {
            int e = tid + it * 256;
            int s = e >> 8, r5 = e & 255;
            int x = r5 >> 1, q = r5 & 1;
            int gy = y0 - 1 + s;
            int gyc = gy < 0 ? 0 : (gy > 127 ? 127 : gy);
            const char* src = srcA + ((size_t)gyc * 128 + x) * 32 + q * 16;
            int ri = s * 130 + x + 1;
            uint32_t dst = aB + ri * 32 + ((q ^ (ri >> 2)) & 1) * 16;
            CPA16(dst, src, ((unsigned)gy < 128u) ? 16 : 0);
        }
        uint32_t bBf = sb + C1_OFF_B + d * C1_B_BUF;
        const char* srcB = wBase + (size_t)c * C1_B_BUF;
        for (int e = tid; e < 1152; e += 256)
            CPA16(bBf + e * 16, srcB + e * 16, 16);
        CP_COMMIT();
    };

    stage(0, 0);
    for (int c = 0; c < 8; c++) {
        if (c < 7) { stage(c + 1, (c + 1) & 1); CP_WAIT1(); }
        else CP_WAIT0();
        __syncthreads();

        const uint32_t aBuf = sb + (c & 1) * C1_A_BUF;
        const uint32_t bBuf = bSwz + (c & 1) * C1_B_BUF;
#pragma unroll
        for (int dy = 0; dy < 3; dy++) {
#pragma unroll
            for (int dx = 0; dx < 3; dx++) {
                const int tap = dy * 3 + dx;
                uint32_t bh[8];
                uint32_t bt = bBuf + tap * 2048;
                LDSM4(bh, bt);
                LDSM4(bh + 4, bt + 512);
                uint32_t a[16];
#pragma unroll
                for (int mt = 0; mt < 4; mt++) {
                    int rt = riA[mt] + dy * 130 + dx;
                    uint32_t ad = aBuf + rt * 32 + ((qA ^ (rt >> 2)) & 1) * 16;
                    LDSM4(a + mt * 4, ad);
                }
#pragma unroll
                for (int mt = 0; mt < 4; mt++)
#pragma unroll
                    for (int nt = 0; nt < 4; nt++)
                        MMA16816(C[mt][nt], a + mt * 4, bh[nt * 2], bh[nt * 2 + 1]);
            }
        }
        __syncthreads();
    }

    {
        const int g2 = lane >> 2, t4 = lane & 3;
#pragma unroll
        for (int mt = 0; mt < 4; mt++) {
#pragma unroll
            for (int nt = 0; nt < 4; nt++) {
                int px = wpx + mt * 16 + g2;
                int oc = wn + nt * 8 + t4 * 2;
                smemT[oc * 265 + px] = C[mt][nt][0];
                smemT[(oc + 1) * 265 + px] = C[mt][nt][1];
                smemT[oc * 265 + px + 8] = C[mt][nt][2];
                smemT[(oc + 1) * 265 + px + 8] = C[mt][nt][3];
            }
        }
    }
    __syncthreads();
    for (int e = tid; e < 1024; e += 256) {
        int c = e >> 8, px = e & 255;
        int gy = y0 + (px >> 7), x = px & 127;
        uint32_t uh[8];
#pragma unroll
        for (int jp = 0; jp < 8; jp++) {
            __half oh[2];
#pragma unroll
            for (int t = 0; t < 2; t++) {
                int oc = c * 16 + 2 * jp + t;
                float val = 0.f;
                if (oc < C1) {
                    float acc = smemT[oc * 265 + px];
                    val = fmaxf(acc + smP[oc], 0.f) * smP[64 + oc] + smP[128 + oc];
                }
                oh[t] = __float2half(val);
            }
            uh[jp] = pack_h2(oh[0], oh[1]);
        }
        float4* dst = ((float4*)g_hp) + (((size_t)(b * 4 + c) * 128 + gy) * 128 + x) * 2;
        dst[0] = make_float4(__uint_as_float(uh[0]), __uint_as_float(uh[1]),
                             __uint_as_float(uh[2]), __uint_as_float(uh[3]));
        dst[1] = make_float4(__uint_as_float(uh[4]), __uint_as_float(uh[5]),
                             __uint_as_float(uh[6]), __uint_as_float(uh[7]));
    }
}

// ---------------------------------------------------------------------------
// conv2 mma (unchanged): M=512, N=32 (18 used), K=4x9x16. grid=256.
// ---------------------------------------------------------------------------
#define C2_A_BUF 24960
#define C2_OFF_B 49920
#define C2_B_BUF 9216
#define C2_SMEM 68352

__global__ void __launch_bounds__(256, 2) conv2_mma_kernel(const float* __restrict__ b2)
{
    extern __shared__ char smem[];
    float* smemT = (float*)smem;
    const uint32_t sb = smem_u32(smem);
    const int tid = threadIdx.x;
    const int lane = tid & 31;
    const int warp = tid >> 5;
    const int b = blockIdx.x >> 5;
    const int y0 = (blockIdx.x & 31) * 4;
    const int wpx = warp * 64;

    if (tid < 48) {
        int q = tid & 1, col = (tid >> 1) & 1, s = (tid >> 2) % 6, d = tid >= 24 ? 1 : 0;
        int ri = s * 130 + (col ? 129 : 0);
        *(float4*)(smem + d * C2_A_BUF + ri * 32 + q * 16) =
            make_float4(0.f, 0.f, 0.f, 0.f);
    }

    const int rA = (lane & 7) + ((lane >> 3) & 1) * 8;
    const int qA = lane >> 4;
    int riA[4];
#pragma unroll
    for (int mt = 0; mt < 4; mt++) {
        int px = wpx + mt * 16 + rA;
        riA[mt] = (px >> 7) * 130 + (px & 127);
    }
    const int ocB = (lane & 7) + ((lane >> 4) << 3);
    const int qB = (lane >> 3) & 1;
    const uint32_t bSwz =
        sb + C2_OFF_B + (uint32_t)ocB * 32 + (uint32_t)((qB ^ (ocB >> 2)) & 1) * 16;

    float C[4][4][4];
#pragma unroll
    for (int i = 0; i < 4; i++)
#pragma unroll
        for (int j = 0; j < 4; j++)
#pragma unroll
            for (int k = 0; k < 4; k++) C[i][j][k] = 0.f;

    const char* hpBase = (const char*)g_hp;
    const char* wBase = (const char*)g_w2p;

    auto stage = [&](int c, int d) {
        const char* srcA = hpBase + (size_t)(b * 4 + c) * (128 * 128 * 32);
        uint32_t aB = sb + d * C2_A_BUF;
#pragma unroll
        for (int it = 0; it < 6; it++) {
            int e = tid + it * 256;
            int s = e >> 8, r5 = e & 255;
            int x = r5 >> 1, q = r5 & 1;
            int gy = y0 - 1 + s;
            int gyc = gy < 0 ? 0 : (gy > 127 ? 127 : gy);
            const char* src = srcA + ((size_t)gyc * 128 + x) * 32 + q * 16;
            int ri = s * 130 + x + 1;
            uint32_t dst = aB + ri * 32 + ((q ^ (ri >> 2)) & 1) * 16;
            CPA16(dst, src, ((unsigned)gy < 128u) ? 16 : 0);
        }
        uint32_t bBf = sb + C2_OFF_B + d * C2_B_BUF;
        const char* srcB = wBase + (size_t)c * C2_B_BUF;
        for (int e = tid; e < 576; e += 256)
            CPA16(bBf + e * 16, srcB + e * 16, 16);
        CP_COMMIT();
    };

    stage(0, 0);
    for (int c = 0; c < 4; c++) {
        if (c < 3) { stage(c + 1, (c + 1) & 1); CP_WAIT1(); }
        else CP_WAIT0();
        __syncthreads();

        const uint32_t aBuf = sb + (c & 1) * C2_A_BUF;
        const uint32_t bBuf = bSwz + (c & 1) * C2_B_BUF;
#pragma unroll
        for (int dy = 0; dy < 3; dy++) {
#pragma unroll
            for (int dx = 0; dx < 3; dx++) {
                const int tap = dy * 3 + dx;
                uint32_t bh[8];
                uint32_t bt = bBuf + tap * 1024;
                LDSM4(bh, bt);
                LDSM4(bh + 4, bt + 512);
                uint32_t a[16];
#pragma unroll
                for (int mt = 0; mt < 4; mt++) {
                    int rt = riA[mt] + dy * 130 + dx;
                    uint32_t ad = aBuf + rt * 32 + ((qA ^ (rt >> 2)) & 1) * 16;
                    LDSM4(a + mt * 4, ad);
                }
#pragma unroll
                for (int mt = 0; mt < 4; mt++)
#pragma unroll
                    for (int nt = 0; nt < 4; nt++)
                        MMA16816(C[mt][nt], a + mt * 4, bh[nt * 2], bh[nt * 2 + 1]);
            }
        }
        __syncthreads();
    }

    {
        const int g2 = lane >> 2, t4 = lane & 3;
#pragma unroll
        for (int mt = 0; mt < 4; mt++) {
#pragma unroll
            for (int nt = 0; nt < 4; nt++) {
                int px = wpx + mt * 16 + g2;
                int oc = nt * 8 + t4 * 2;
                smemT[oc * 516 + px] = C[mt][nt][0];
                smemT[(oc + 1) * 516 + px] = C[mt][nt][1];
                smemT[oc * 516 + px + 8] = C[mt][nt][2];
                smemT[(oc + 1) * 516 + px + 8] = C[mt][nt][3];
            }
        }
    }
    __syncthreads();
    for (int e = tid; e < C2 * 128; e += 256) {
        int oc = e >> 7, pq = e & 127;
        int px0 = pq * 4;
        int gy = y0 + (px0 >> 7), x = px0 & 127;
        float bv = b2[oc];
        float4 v = *(float4*)(smemT + oc * 516 + px0);
        v.x += bv; v.y += bv; v.z += bv; v.w += bv;
        *(float4*)(g_cond + (((size_t)b * C2 + oc) * NH + gy) * NW + x) = v;
    }
}

// ---------------------------------------------------------------------------
// translate — exact R4 version (1 cell/thread; measured 25.2us)
// ---------------------------------------------------------------------------
__global__ __launch_bounds__(256) void translate_kernel(
    const float* __restrict__ image, float* __restrict__ out)
{
    const int x4 = threadIdx.x;
    const int cellY = blockIdx.x * 2 + threadIdx.y;
    const int ch = blockIdx.y;
    const int b = blockIdx.z;
    const int g = ch / 3;

    float wk[9];
    const float* cond_b = g_cond + ((size_t)b * C2 + g * 9) * NH * NW;
#pragma unroll
    for (int k = 0; k < 9; k++)
        wk[k] = cond_b[(size_t)k * NH * NW + (size_t)cellY * NW + x4];

    const float4* img4 = (const float4*)image + (size_t)(b * 6 + ch) * HH * (WW / 4);
    float4* out4 = (float4*)out + (size_t)(b * 6 + ch) * HH * (WW / 4);

#pragma unroll
    for (int r = 0; r < 4; r++) {
        int y = cellY * 4 + r;
        float4 acc = make_float4(0.f, 0.f, 0.f, 0.f);
#pragma unroll
        for (int i = 0; i < 3; i++) {
            int xf = x4 + i - 1;
            if ((unsigned)xf >= (unsigned)(WW / 4)) continue;
#pragma unroll
            for (int j = 0; j < 3; j++) {
                int yy = y + j * 4 - 4;
                if ((unsigned)yy >= (unsigned)HH) continue;
                float w = wk[i * 3 + j];
                float4 v = img4[(size_t)yy * (WW / 4) + xf];
                acc.x += v.x * w; acc.y += v.y * w;
                acc.z += v.z * w; acc.w += v.w * w;
            }
        }
        out4[(size_t)y * (WW / 4) + x4] = acc;
    }
}

// ---------------------------------------------------------------------------
extern "C" void kernel_launch(void* const* d_in, const int* in_sizes, int n_in,
                              void* d_out, int out_size)
{
    const float* image = (const float*)d_in[0];
    const float* ctrl  = (const float*)d_in[1];
    const float* w1    = (const float*)d_in[2];
    const float* b1    = (const float*)d_in[3];
    const float* gamma = (const float*)d_in[4];
    const float* beta  = (const float*)d_in[5];
    const float* mean  = (const float*)d_in[6];
    const float* var   = (const float*)d_in[7];
    const float* w2    = (const float*)d_in[8];
    const float* b2    = (const float*)d_in[9];
    float* out = (float*)d_out;

    static int smem_set = 0;
    if (!smem_set) {
        cudaFuncSetAttribute(conv1_mma_kernel,
                             cudaFuncAttributeMaxDynamicSharedMemorySize, C1_SMEM);
        cudaFuncSetAttribute(conv2_mma_kernel,
                             cudaFuncAttributeMaxDynamicSharedMemorySize, C2_SMEM);
        smem_set = 1;
    }

    prep_all_kernel<<<2048 + 360, 256>>>(ctrl, w1, w2);
    conv1_mma_kernel<<<BB * 64, 256, C1_SMEM>>>(b1, gamma, beta, mean, var);
    conv2_mma_kernel<<<BB * 32, 256, C2_SMEM>>>(b2);
    translate_kernel<<<dim3(64, 6, BB), dim3(128, 2)>>>(image, out);
}